// round 10
// baseline (speedup 1.0000x reference)
#include <cuda_runtime.h>
#include <cuda_bf16.h>
#include <stdint.h>
#include <math.h>

#define T_TOTAL 65536
#define D_MODEL 256
#define D_INNER 512
#define HEADDIM 64
#define NHEADS 8
#define DSTATE 128
#define CHUNK 128
#define CONV_DIM 768
#define D_IN_PROJ 1288
#define NCHUNK 512
#define NEGV -10000.0f

// ---------------- scratch ----------------
static __device__ float g_xn[T_TOTAL * D_MODEL];
static __device__ float g_zx[T_TOTAL * D_IN_PROJ];
static __device__ float g_dtraw[T_TOTAL * NHEADS];
static __device__ float g_dt[T_TOTAL * NHEADS];
static __device__ float g_xh[T_TOTAL * D_INNER];
static __device__ float g_Bmat[T_TOTAL * DSTATE];
static __device__ float g_Cmat[T_TOTAL * DSTATE];
static __device__ float g_a[T_TOTAL * NHEADS];
static __device__ float g_Acum[T_TOTAL * NHEADS];
static __device__ float g_cd[NCHUNK * NHEADS];
static __device__ float g_M[NCHUNK * CHUNK * CHUNK];
static __device__ float g_cs[NCHUNK * NHEADS * HEADDIM * DSTATE];
static __device__ float g_ps[NCHUNK * NHEADS * HEADDIM * DSTATE];
static __device__ float g_y[T_TOTAL * D_INNER];
static __device__ float g_scale[T_TOTAL];

// ---------------- helpers ----------------
__device__ __forceinline__ float to_tf32(float f) {
    unsigned u; asm("cvt.rna.tf32.f32 %0, %1;" : "=r"(u) : "f"(f));
    return __uint_as_float(u);
}
__device__ __forceinline__ float4 cvt4(float4 v) {
    return make_float4(to_tf32(v.x), to_tf32(v.y), to_tf32(v.z), to_tf32(v.w));
}

#define LDSM4(r0, r1, r2, r3, addr) \
    asm volatile("ldmatrix.sync.aligned.m8n8.x4.shared.b16 {%0,%1,%2,%3}, [%4];" \
                 : "=r"(r0), "=r"(r1), "=r"(r2), "=r"(r3) : "r"(addr))

#define MMA_TF32(d, a, b0, b1) \
    asm volatile("mma.sync.aligned.m16n8k8.row.col.f32.tf32.tf32.f32 " \
                 "{%0,%1,%2,%3}, {%4,%5,%6,%7}, {%8,%9}, {%0,%1,%2,%3};" \
                 : "+f"(d[0]), "+f"(d[1]), "+f"(d[2]), "+f"(d[3]) \
                 : "r"(a[0]), "r"(a[1]), "r"(a[2]), "r"(a[3]), "r"(b0), "r"(b1))

// ---------------- LayerNorm + fused fp32 dt_raw ----------------
__global__ __launch_bounds__(256) void k_ln(const float* __restrict__ x,
                                            const float* __restrict__ gamma,
                                            const float* __restrict__ beta,
                                            const float* __restrict__ W) {
    int t = blockIdx.x, tid = threadIdx.x;
    int warp = tid >> 5, lane = tid & 31;
    float v = x[t * 256 + tid];
    float s = v, s2 = v * v;
    #pragma unroll
    for (int o = 16; o; o >>= 1) {
        s  += __shfl_xor_sync(0xffffffffu, s, o);
        s2 += __shfl_xor_sync(0xffffffffu, s2, o);
    }
    __shared__ float ws[8], ws2[8];
    if (lane == 0) { ws[warp] = s; ws2[warp] = s2; }
    __syncthreads();
    __shared__ float s_mu, s_rstd;
    if (tid == 0) {
        float a = 0.f, b = 0.f;
        #pragma unroll
        for (int i = 0; i < 8; i++) { a += ws[i]; b += ws2[i]; }
        float mu = a * (1.f / 256.f);
        float var = b * (1.f / 256.f) - mu * mu;
        s_mu = mu; s_rstd = rsqrtf(var + 1e-5f);
    }
    __syncthreads();
    float xn = (v - s_mu) * s_rstd * gamma[tid] + beta[tid];
    g_xn[t * 256 + tid] = xn;
    __shared__ float wsum[8][8];
    #pragma unroll
    for (int h = 0; h < 8; h++) {
        float d = xn * W[(long)(1280 + h) * 256 + tid];
        #pragma unroll
        for (int o = 16; o; o >>= 1) d += __shfl_xor_sync(0xffffffffu, d, o);
        if (lane == 0) wsum[h][warp] = d;
    }
    __syncthreads();
    if (tid < 8) {
        float d = 0.f;
        #pragma unroll
        for (int w2 = 0; w2 < 8; w2++) d += wsum[tid][w2];
        g_dtraw[t * 8 + tid] = d;
    }
}

// ---------------- tf32 GEMM (double-buffered): C[M,N]=A[M,K]*B[N,K]^T, batched ----------------
__global__ __launch_bounds__(256) void k_gemm_tc(const float* __restrict__ A,
                                                 const float* __restrict__ B,
                                                 float* __restrict__ C,
                                                 int M, int N, int K,
                                                 long sA, long sB, long sC) {
    extern __shared__ float smg[];   // [A0|A1|B0|B1], 4608 floats each
    A += (long)blockIdx.z * sA;
    B += (long)blockIdx.z * sB;
    C += (long)blockIdx.z * sC;
    const int tid = threadIdx.x;
    const int warp = tid >> 5, lane = tid & 31;
    const int wm = (warp >> 1) * 32;
    const int wn = (warp & 1) * 64;
    const long m0 = (long)blockIdx.y * 128;
    const int n0 = blockIdx.x * 128;
    const int lr = tid >> 1;
    const int lc = tid & 1;
    const int lr16 = lane & 15;
    const int khalf = (lane >> 4) * 4;
    float acc[2][8][4] = {};
    const int ntiles = K >> 5;
    const bool nvalid = (n0 + lr) < N;
    const float* Arow = A + (m0 + lr) * K;
    const float* Brow = B + (long)(n0 + lr) * K;
    float4 va[4], vb[4];

    #pragma unroll
    for (int i = 0; i < 4; i++) {
        int cc = (lc + 2 * i) * 4;
        va[i] = *(const float4*)(Arow + cc);
        vb[i] = nvalid ? *(const float4*)(Brow + cc) : make_float4(0.f, 0.f, 0.f, 0.f);
    }
    #pragma unroll
    for (int i = 0; i < 4; i++) {
        int cc = (lc + 2 * i) * 4;
        *(float4*)&smg[lr * 36 + cc]        = cvt4(va[i]);
        *(float4*)&smg[9216 + lr * 36 + cc] = cvt4(vb[i]);
    }
    __syncthreads();

    for (int kt = 0; kt < ntiles; kt++) {
        if (kt + 1 < ntiles) {
            int k0 = (kt + 1) << 5;
            #pragma unroll
            for (int i = 0; i < 4; i++) {
                int cc = (lc + 2 * i) * 4;
                va[i] = *(const float4*)(Arow + k0 + cc);
                vb[i] = nvalid ? *(const float4*)(Brow + k0 + cc) : make_float4(0.f, 0.f, 0.f, 0.f);
            }
        }
        const unsigned sAb = (unsigned)__cvta_generic_to_shared(smg + (kt & 1) * 4608);
        const unsigned sBb = (unsigned)__cvta_generic_to_shared(smg + 9216 + (kt & 1) * 4608);
        #pragma unroll
        for (int kk = 0; kk < 32; kk += 8) {
            unsigned af[2][4];
            #pragma unroll
            for (int mt = 0; mt < 2; mt++) {
                unsigned ad = sAb + (unsigned)(((wm + mt * 16 + lr16) * 36 + kk + khalf) * 4);
                LDSM4(af[mt][0], af[mt][1], af[mt][2], af[mt][3], ad);
            }
            unsigned bf[4][4];
            #pragma unroll
            for (int nt = 0; nt < 4; nt++) {
                unsigned bd = sBb + (unsigned)(((wn + nt * 16 + lr16) * 36 + kk + khalf) * 4);
                LDSM4(bf[nt][0], bf[nt][1], bf[nt][2], bf[nt][3], bd);
            }
            #pragma unroll
            for (int mt = 0; mt < 2; mt++)
                #pragma unroll
                for (int nt = 0; nt < 4; nt++) {
                    MMA_TF32(acc[mt][nt * 2 + 0], af[mt], bf[nt][0], bf[nt][2]);
                    MMA_TF32(acc[mt][nt * 2 + 1], af[mt], bf[nt][1], bf[nt][3]);
                }
        }
        if (kt + 1 < ntiles) {
            float* dA = smg + ((kt + 1) & 1) * 4608;
            float* dB = smg + 9216 + ((kt + 1) & 1) * 4608;
            #pragma unroll
            for (int i = 0; i < 4; i++) {
                int cc = (lc + 2 * i) * 4;
                *(float4*)&dA[lr * 36 + cc] = cvt4(va[i]);
                *(float4*)&dB[lr * 36 + cc] = cvt4(vb[i]);
            }
            __syncthreads();
        }
    }
    const int g = lane >> 2, tq = lane & 3;
    #pragma unroll
    for (int mt = 0; mt < 2; mt++) {
        long m = m0 + wm + mt * 16 + g;
        #pragma unroll
        for (int j = 0; j < 8; j++) {
            int n = n0 + wn + j * 8 + 2 * tq;
            if (n < N) {
                *(float2*)&C[m * N + n]       = make_float2(acc[mt][j][0], acc[mt][j][1]);
                *(float2*)&C[(m + 8) * N + n] = make_float2(acc[mt][j][2], acc[mt][j][3]);
            }
        }
    }
}

// ---------------- out_proj GEMM with fused gated-RMSNorm A operand ----------------
// out[M,256] = G[M,512] * W[256,512]^T,  G[t][c] = y*silu(z)*scale[t]*norm_w[c]
__device__ __forceinline__ float4 gv_fill(long ry, long rz, int k, float sc,
                                          const float* __restrict__ nw) {
    float4 y = *(const float4*)(g_y + ry + k);
    float4 z = *(const float4*)(g_zx + rz + k);
    float4 w = *(const float4*)(nw + k);
    float4 r;
    r.x = y.x * (z.x / (1.f + __expf(-z.x))) * sc * w.x;
    r.y = y.y * (z.y / (1.f + __expf(-z.y))) * sc * w.y;
    r.z = y.z * (z.z / (1.f + __expf(-z.z))) * sc * w.z;
    r.w = y.w * (z.w / (1.f + __expf(-z.w))) * sc * w.w;
    return r;
}

__global__ __launch_bounds__(256) void k_gemm_out(const float* __restrict__ B,
                                                  const float* __restrict__ norm_w,
                                                  float* __restrict__ C) {
    extern __shared__ float smg[];
    const int tid = threadIdx.x;
    const int warp = tid >> 5, lane = tid & 31;
    const int wm = (warp >> 1) * 32;
    const int wn = (warp & 1) * 64;
    const long m0 = (long)blockIdx.y * 128;
    const int n0 = blockIdx.x * 128;
    const int lr = tid >> 1;
    const int lc = tid & 1;
    const int lr16 = lane & 15;
    const int khalf = (lane >> 4) * 4;
    float acc[2][8][4] = {};
    const int ntiles = D_INNER >> 5;   // 16
    const long ry = (m0 + lr) * 512;
    const long rz = (m0 + lr) * (long)D_IN_PROJ;
    const float sc = g_scale[m0 + lr];
    const float* Brow = B + (long)(n0 + lr) * D_INNER;
    float4 va[4], vb[4];

    #pragma unroll
    for (int i = 0; i < 4; i++) {
        int cc = (lc + 2 * i) * 4;
        va[i] = gv_fill(ry, rz, cc, sc, norm_w);
        vb[i] = *(const float4*)(Brow + cc);
    }
    #pragma unroll
    for (int i = 0; i < 4; i++) {
        int cc = (lc + 2 * i) * 4;
        *(float4*)&smg[lr * 36 + cc]        = cvt4(va[i]);
        *(float4*)&smg[9216 + lr * 36 + cc] = cvt4(vb[i]);
    }
    __syncthreads();

    for (int kt = 0; kt < ntiles; kt++) {
        if (kt + 1 < ntiles) {
            int k0 = (kt + 1) << 5;
            #pragma unroll
            for (int i = 0; i < 4; i++) {
                int cc = (lc + 2 * i) * 4;
                va[i] = gv_fill(ry, rz, k0 + cc, sc, norm_w);
                vb[i] = *(const float4*)(Brow + k0 + cc);
            }
        }
        const unsigned sAb = (unsigned)__cvta_generic_to_shared(smg + (kt & 1) * 4608);
        const unsigned sBb = (unsigned)__cvta_generic_to_shared(smg + 9216 + (kt & 1) * 4608);
        #pragma unroll
        for (int kk = 0; kk < 32; kk += 8) {
            unsigned af[2][4];
            #pragma unroll
            for (int mt = 0; mt < 2; mt++) {
                unsigned ad = sAb + (unsigned)(((wm + mt * 16 + lr16) * 36 + kk + khalf) * 4);
                LDSM4(af[mt][0], af[mt][1], af[mt][2], af[mt][3], ad);
            }
            unsigned bf[4][4];
            #pragma unroll
            for (int nt = 0; nt < 4; nt++) {
                unsigned bd = sBb + (unsigned)(((wn + nt * 16 + lr16) * 36 + kk + khalf) * 4);
                LDSM4(bf[nt][0], bf[nt][1], bf[nt][2], bf[nt][3], bd);
            }
            #pragma unroll
            for (int mt = 0; mt < 2; mt++)
                #pragma unroll
                for (int nt = 0; nt < 4; nt++) {
                    MMA_TF32(acc[mt][nt * 2 + 0], af[mt], bf[nt][0], bf[nt][2]);
                    MMA_TF32(acc[mt][nt * 2 + 1], af[mt], bf[nt][1], bf[nt][3]);
                }
        }
        if (kt + 1 < ntiles) {
            float* dA = smg + ((kt + 1) & 1) * 4608;
            float* dB = smg + 9216 + ((kt + 1) & 1) * 4608;
            #pragma unroll
            for (int i = 0; i < 4; i++) {
                int cc = (lc + 2 * i) * 4;
                *(float4*)&dA[lr * 36 + cc] = cvt4(va[i]);
                *(float4*)&dB[lr * 36 + cc] = cvt4(vb[i]);
            }
            __syncthreads();
        }
    }
    const int g = lane >> 2, tq = lane & 3;
    #pragma unroll
    for (int mt = 0; mt < 2; mt++) {
        long m = m0 + wm + mt * 16 + g;
        #pragma unroll
        for (int j = 0; j < 8; j++) {
            int n = n0 + wn + j * 8 + 2 * tq;
            if (n < D_MODEL) {
                *(float2*)&C[m * D_MODEL + n]       = make_float2(acc[mt][j][0], acc[mt][j][1]);
                *(float2*)&C[(m + 8) * D_MODEL + n] = make_float2(acc[mt][j][2], acc[mt][j][3]);
            }
        }
    }
}

// ---------------- tiled conv + SiLU + splits + dt/a (32-token tiles) ----------------
__global__ __launch_bounds__(256) void k_conv(const float* __restrict__ conv_w,
                                              const float* __restrict__ conv_b,
                                              const float* __restrict__ dt_bias,
                                              const float* __restrict__ A_log,
                                              const int* __restrict__ pts) {
    extern __shared__ float s_in[];          // 35 * 256
    __shared__ int s_v[32];
    int cx = blockIdx.x, tid = threadIdx.x;
    long t0 = (long)blockIdx.y * 32;
    int c0 = cx * 256;
    for (int i = tid; i < 35 * 64; i += 256) {
        int row = i >> 6, c4 = (i & 63) * 4;
        long t = t0 - 3 + row;
        float4 v = (t >= 0) ? *(const float4*)(g_zx + t * D_IN_PROJ + 512 + c0 + c4)
                            : make_float4(0.f, 0.f, 0.f, 0.f);
        *(float4*)&s_in[row * 256 + c4] = v;
    }
    if (tid < 32) {
        int t = (int)t0 + tid;
        int b = 0; bool s0 = false, s1 = false, s2 = false;
        #pragma unroll
        for (int j = 0; j < 8; j++) {
            if (b == t) s0 = true;
            if (b == t - 1) s1 = true;
            if (b == t - 2) s2 = true;
            b += pts[j];
        }
        bool v1 = !s0, v2 = v1 && !s1, v3 = v2 && !s2;
        s_v[tid] = (v1 ? 1 : 0) | (v2 ? 2 : 0) | (v3 ? 4 : 0) | (s0 ? 8 : 0);
    }
    __syncthreads();
    if (cx == 0) {
        int tok = tid >> 3, h = tid & 7;
        long t = t0 + tok;
        float xr = g_dtraw[t * 8 + h] + dt_bias[h];
        float dt = (xr > 20.f) ? xr : log1pf(expf(xr));
        g_dt[t * 8 + h] = dt;
        float a = -expf(A_log[h]) * dt;
        if (s_v[tok] & 8) a = NEGV;
        g_a[(((int)t >> 7) * 8 + h) * 128 + ((int)t & 127)] = a;
    }
    int ch = tid;
    float4 w = *(const float4*)(conv_w + (c0 + ch) * 4);
    float bias = conv_b[c0 + ch];
    #pragma unroll 4
    for (int tok = 0; tok < 32; tok++) {
        int m = s_v[tok];
        float acc = bias + s_in[(tok + 3) * 256 + ch] * w.w;
        if (m & 1) acc += s_in[(tok + 2) * 256 + ch] * w.z;
        if (m & 2) acc += s_in[(tok + 1) * 256 + ch] * w.y;
        if (m & 4) acc += s_in[(tok + 0) * 256 + ch] * w.x;
        float v = acc / (1.f + __expf(-acc));
        long t = t0 + tok;
        if (cx < 2) g_xh[t * 512 + c0 + ch] = v;
        else if (ch < 128) g_Bmat[t * 128 + ch] = v;
        else g_Cmat[t * 128 + (ch - 128)] = v;
    }
}

// ---------------- per-(chunk,head) cumsum of a ----------------
__global__ __launch_bounds__(256) void k_cumsum() {
    int idx = blockIdx.x * 8 + (threadIdx.x >> 5);
    int lane = threadIdx.x & 31;
    float4 v4 = *(const float4*)(g_a + idx * 128 + lane * 4);
    float p0 = v4.x, p1 = p0 + v4.y, p2 = p1 + v4.z, p3 = p2 + v4.w;
    float e = p3;
    #pragma unroll
    for (int o = 1; o < 32; o <<= 1) {
        float n = __shfl_up_sync(0xffffffffu, e, o);
        if (lane >= o) e += n;
    }
    float ex = e - p3;
    *(float4*)(g_Acum + idx * 128 + lane * 4) =
        make_float4(ex + p0, ex + p1, ex + p2, ex + p3);
    if (lane == 31) g_cd[idx] = expf(ex + p3);
}

// ---------------- k_chunk: Ydiag (+D*xh) and chunk_states via tf32 mma ----------------
__global__ __launch_bounds__(256) void k_chunk(const float* __restrict__ Dp) {
    extern __shared__ float sm[];
    float* sP   = sm;                   // 128 x 132
    float* sXT  = sm + 128 * 132;       // 64 x 132
    float* sAc  = sXT + 64 * 132;
    float* sDt  = sAc + 128;
    float* sDec = sDt + 128;
    int c = blockIdx.x, h = blockIdx.y, tid = threadIdx.x;
    int warp = tid >> 5, lane = tid & 31;
    int lr16 = lane & 15, khalf = (lane >> 4) * 4;
    const unsigned sPb = (unsigned)__cvta_generic_to_shared(sP);
    const unsigned sXb = (unsigned)__cvta_generic_to_shared(sXT);

    if (tid < 128) {
        sAc[tid] = g_Acum[(c * 8 + h) * 128 + tid];
        sDt[tid] = g_dt[((long)c * 128 + tid) * 8 + h];
    }
    __syncthreads();
    float alast = sAc[127];
    if (tid < 128) sDec[tid] = __expf(alast - sAc[tid]);
    const float* Xg = g_xh + (long)c * 128 * 512 + h * 64;
    for (int i = tid; i < 8192; i += 256) {
        int s = i >> 6, p = i & 63;
        sXT[p * 132 + s] = to_tf32(Xg[s * 512 + p] * sDt[s]);
    }
    const float* Mg = g_M + (long)c * 16384;
    for (int i = tid; i < 16384; i += 256) {
        int q = i >> 7, s = i & 127;
        sP[q * 132 + s] = (s <= q) ? to_tf32(Mg[i] * __expf(sAc[q] - sAc[s])) : 0.f;
    }
    __syncthreads();

    float acc[8][4] = {};
    int wm = warp * 16;
    for (int kk = 0; kk < 128; kk += 8) {
        unsigned af[4];
        unsigned ad = sPb + (unsigned)(((wm + lr16) * 132 + kk + khalf) * 4);
        LDSM4(af[0], af[1], af[2], af[3], ad);
        unsigned bf[4][4];
        #pragma unroll
        for (int nt = 0; nt < 4; nt++) {
            unsigned bd = sXb + (unsigned)(((nt * 16 + lr16) * 132 + kk + khalf) * 4);
            LDSM4(bf[nt][0], bf[nt][1], bf[nt][2], bf[nt][3], bd);
        }
        #pragma unroll
        for (int nt = 0; nt < 4; nt++) {
            MMA_TF32(acc[nt * 2 + 0], af, bf[nt][0], bf[nt][2]);
            MMA_TF32(acc[nt * 2 + 1], af, bf[nt][1], bf[nt][3]);
        }
    }
    float Dh = Dp[h];
    int g = lane >> 2, tq = lane & 3;
    {
        long r0 = ((long)c * 128 + wm + g) * 512 + h * 64;
        long r1 = r0 + 8 * 512;
        #pragma unroll
        for (int j = 0; j < 8; j++) {
            int n = j * 8 + 2 * tq;
            float2 x0 = *(const float2*)&g_xh[r0 + n];
            float2 x1 = *(const float2*)&g_xh[r1 + n];
            *(float2*)&g_y[r0 + n] = make_float2(acc[j][0] + Dh * x0.x, acc[j][1] + Dh * x0.y);
            *(float2*)&g_y[r1 + n] = make_float2(acc[j][2] + Dh * x1.x, acc[j][3] + Dh * x1.y);
        }
    }
    __syncthreads();

    for (int i = tid; i < 8192; i += 256) {
        int p = i >> 7, s = i & 127;
        sXT[p * 132 + s] = to_tf32(sXT[p * 132 + s] * sDec[s]);
    }
    const float* Bg = g_Bmat + (long)c * 16384;
    for (int i = tid; i < 16384; i += 256) {
        int s = i >> 7, n = i & 127;
        sP[n * 132 + s] = to_tf32(Bg[i]);
    }
    __syncthreads();

    float acc2[8][4] = {};
    int wm2 = (warp & 3) * 16, wn2 = (warp >> 2) * 64;
    for (int kk = 0; kk < 128; kk += 8) {
        unsigned af[4];
        unsigned ad = sXb + (unsigned)(((wm2 + lr16) * 132 + kk + khalf) * 4);
        LDSM4(af[0], af[1], af[2], af[3], ad);
        unsigned bf[4][4];
        #pragma unroll
        for (int nt = 0; nt < 4; nt++) {
            unsigned bd = sPb + (unsigned)(((wn2 + nt * 16 + lr16) * 132 + kk + khalf) * 4);
            LDSM4(bf[nt][0], bf[nt][1], bf[nt][2], bf[nt][3], bd);
        }
        #pragma unroll
        for (int nt = 0; nt < 4; nt++) {
            MMA_TF32(acc2[nt * 2 + 0], af, bf[nt][0], bf[nt][2]);
            MMA_TF32(acc2[nt * 2 + 1], af, bf[nt][1], bf[nt][3]);
        }
    }
    float* So = g_cs + ((long)c * 8 + h) * 8192;
    #pragma unroll
    for (int j = 0; j < 8; j++) {
        int n = wn2 + j * 8 + 2 * tq;
        int p = wm2 + g;
        *(float2*)&So[p * 128 + n]       = make_float2(acc2[j][0], acc2[j][1]);
        *(float2*)&So[(p + 8) * 128 + n] = make_float2(acc2[j][2], acc2[j][3]);
    }
}

// ---------------- inter-chunk scan ----------------
__global__ __launch_bounds__(256) void k_scan() {
    int e = blockIdx.x * 256 + threadIdx.x;
    int h = e >> 13;
    float st = 0.f;
    const float* cdp = g_cd + h;
    for (int c = 0; c < NCHUNK; c++) {
        g_ps[c * 65536 + e] = st;
        st = st * cdp[c * 8] + g_cs[c * 65536 + e];
    }
}

// ---------------- k_yoff via tf32 mma ----------------
__global__ __launch_bounds__(256) void k_yoff() {
    extern __shared__ float sm[];
    float* sC  = sm;                    // 128 x 132
    float* sPS = sm + 128 * 132;        // 64 x 132
    float* sAc = sPS + 64 * 132;
    int c = blockIdx.x, h = blockIdx.y, tid = threadIdx.x;
    int warp = tid >> 5, lane = tid & 31;
    int lr16 = lane & 15, khalf = (lane >> 4) * 4;
    const unsigned sCb = (unsigned)__cvta_generic_to_shared(sC);
    const unsigned sSb = (unsigned)__cvta_generic_to_shared(sPS);

    if (tid < 128) sAc[tid] = g_Acum[(c * 8 + h) * 128 + tid];
    const float* Cg = g_Cmat + (long)c * 16384;
    for (int i = tid; i < 16384; i += 256) {
        int q = i >> 7, n = i & 127;
        sC[q * 132 + n] = to_tf32(Cg[i]);
    }
    const float* Pg = g_ps + ((long)c * 8 + h) * 8192;
    for (int i = tid; i < 8192; i += 256) {
        int p = i >> 7, n = i & 127;
        sPS[p * 132 + n] = to_tf32(Pg[i]);
    }
    __syncthreads();

    float acc[8][4] = {};
    int wm = warp * 16;
    for (int kk = 0; kk < 128; kk += 8) {
        unsigned af[4];
        unsigned ad = sCb + (unsigned)(((wm + lr16) * 132 + kk + khalf) * 4);
        LDSM4(af[0], af[1], af[2], af[3], ad);
        unsigned bf[4][4];
        #pragma unroll
        for (int nt = 0; nt < 4; nt++) {
            unsigned bd = sSb + (unsigned)(((nt * 16 + lr16) * 132 + kk + khalf) * 4);
            LDSM4(bf[nt][0], bf[nt][1], bf[nt][2], bf[nt][3], bd);
        }
        #pragma unroll
        for (int nt = 0; nt < 4; nt++) {
            MMA_TF32(acc[nt * 2 + 0], af, bf[nt][0], bf[nt][2]);
            MMA_TF32(acc[nt * 2 + 1], af, bf[nt][1], bf[nt][3]);
        }
    }
    int g = lane >> 2, tq = lane & 3;
    float eq0 = __expf(sAc[wm + g]);
    float eq1 = __expf(sAc[wm + g + 8]);
    long r0 = ((long)c * 128 + wm + g) * 512 + h * 64;
    long r1 = r0 + 8 * 512;
    #pragma unroll
    for (int j = 0; j < 8; j++) {
        int n = j * 8 + 2 * tq;
        float2 y0 = *(const float2*)&g_y[r0 + n];
        float2 y1 = *(const float2*)&g_y[r1 + n];
        *(float2*)&g_y[r0 + n] = make_float2(y0.x + eq0 * acc[j][0], y0.y + eq0 * acc[j][1]);
        *(float2*)&g_y[r1 + n] = make_float2(y1.x + eq1 * acc[j][2], y1.y + eq1 * acc[j][3]);
    }
}

// ---------------- per-token RMS scale (gate fused into out_proj) ----------------
__global__ __launch_bounds__(256) void k_scale() {
    int t = blockIdx.x, tid = threadIdx.x;
    float y0 = g_y[t * 512 + tid];
    float z0 = g_zx[(long)t * D_IN_PROJ + tid];
    float gv0 = y0 * (z0 / (1.f + __expf(-z0)));
    float y1 = g_y[t * 512 + tid + 256];
    float z1 = g_zx[(long)t * D_IN_PROJ + tid + 256];
    float gv1 = y1 * (z1 / (1.f + __expf(-z1)));
    float ss = gv0 * gv0 + gv1 * gv1;
    #pragma unroll
    for (int o = 16; o; o >>= 1) ss += __shfl_xor_sync(0xffffffffu, ss, o);
    __shared__ float ws[8];
    if ((tid & 31) == 0) ws[tid >> 5] = ss;
    __syncthreads();
    if (tid == 0) {
        float a = 0.f;
        #pragma unroll
        for (int i = 0; i < 8; i++) a += ws[i];
        g_scale[t] = rsqrtf(a * (1.f / 512.f) + 1e-5f);
    }
}

// ---------------- launch ----------------
extern "C" void kernel_launch(void* const* d_in, const int* in_sizes, int n_in,
                              void* d_out, int out_size) {
    const float* x         = (const float*)d_in[0];
    const float* ln_gamma  = (const float*)d_in[1];
    const float* ln_beta   = (const float*)d_in[2];
    const float* in_proj_w = (const float*)d_in[3];
    const float* conv_w    = (const float*)d_in[4];
    const float* conv_b    = (const float*)d_in[5];
    const float* dt_bias   = (const float*)d_in[6];
    const float* A_log     = (const float*)d_in[7];
    const float* Dv        = (const float*)d_in[8];
    const float* norm_w    = (const float*)d_in[9];
    const float* out_proj_w= (const float*)d_in[10];
    const int*   pts       = (const int*)d_in[11];
    float* out = (float*)d_out;

    const int SMEM_GEMM  = 4 * 4608 * 4;                               // 73728
    const int SMEM_CONV  = 35 * 256 * 4;                               // 35840
    const int SMEM_CHUNK = (128 * 132 + 64 * 132 + 384) * 4;
    const int SMEM_YOFF  = (128 * 132 + 64 * 132 + 128) * 4;
    cudaFuncSetAttribute(k_gemm_tc,  cudaFuncAttributeMaxDynamicSharedMemorySize, SMEM_GEMM);
    cudaFuncSetAttribute(k_gemm_out, cudaFuncAttributeMaxDynamicSharedMemorySize, SMEM_GEMM);
    cudaFuncSetAttribute(k_conv,  cudaFuncAttributeMaxDynamicSharedMemorySize, SMEM_CONV);
    cudaFuncSetAttribute(k_chunk, cudaFuncAttributeMaxDynamicSharedMemorySize, SMEM_CHUNK);
    cudaFuncSetAttribute(k_yoff,  cudaFuncAttributeMaxDynamicSharedMemorySize, SMEM_YOFF);

    float *p_xn, *p_zx, *p_B, *p_C, *p_M;
    cudaGetSymbolAddress((void**)&p_xn, g_xn);
    cudaGetSymbolAddress((void**)&p_zx, g_zx);
    cudaGetSymbolAddress((void**)&p_B,  g_Bmat);
    cudaGetSymbolAddress((void**)&p_C,  g_Cmat);
    cudaGetSymbolAddress((void**)&p_M,  g_M);

    k_ln<<<T_TOTAL, 256>>>(x, ln_gamma, ln_beta, in_proj_w);
    k_gemm_tc<<<dim3(11, 512, 1), 256, SMEM_GEMM>>>(p_xn, in_proj_w, p_zx,
                                                    T_TOTAL, D_IN_PROJ, D_MODEL, 0, 0, 0);
    k_conv<<<dim3(3, 2048), 256, SMEM_CONV>>>(conv_w, conv_b, dt_bias, A_log, pts);
    k_cumsum<<<512, 256>>>();
    k_gemm_tc<<<dim3(1, 1, 512), 256, SMEM_GEMM>>>(p_C, p_B, p_M,
                                                   128, 128, 128, 16384, 16384, 16384);
    k_chunk<<<dim3(512, 8), 256, SMEM_CHUNK>>>(Dv);
    k_scan<<<256, 256>>>();
    k_yoff<<<dim3(512, 8), 256, SMEM_YOFF>>>();
    k_scale<<<T_TOTAL, 256>>>();
    k_gemm_out<<<dim3(2, 512, 1), 256, SMEM_GEMM>>>(out_proj_w, norm_w, out);
}

// round 11
// speedup vs baseline: 1.1741x; 1.1741x over previous
#include <cuda_runtime.h>
#include <cuda_bf16.h>
#include <stdint.h>
#include <math.h>

#define T_TOTAL 65536
#define D_MODEL 256
#define D_INNER 512
#define HEADDIM 64
#define NHEADS 8
#define DSTATE 128
#define CHUNK 128
#define CONV_DIM 768
#define D_IN_PROJ 1288
#define NCHUNK 512
#define NEGV -10000.0f

// ---------------- scratch ----------------
static __device__ float g_xn[T_TOTAL * D_MODEL];
static __device__ float g_zx[T_TOTAL * D_IN_PROJ];
static __device__ float g_dtraw[T_TOTAL * NHEADS];
static __device__ float g_dt[T_TOTAL * NHEADS];
static __device__ float g_xh[T_TOTAL * D_INNER];
static __device__ float g_Bmat[T_TOTAL * DSTATE];
static __device__ float g_Cmat[T_TOTAL * DSTATE];
static __device__ float g_a[T_TOTAL * NHEADS];
static __device__ float g_Acum[T_TOTAL * NHEADS];
static __device__ float g_cd[NCHUNK * NHEADS];
static __device__ float g_M[NCHUNK * CHUNK * CHUNK];
static __device__ float g_cs[NCHUNK * NHEADS * HEADDIM * DSTATE];
static __device__ float g_ps[NCHUNK * NHEADS * HEADDIM * DSTATE];
static __device__ float g_y[T_TOTAL * D_INNER];
static __device__ float g_g[T_TOTAL * D_INNER];

// ---------------- helpers ----------------
__device__ __forceinline__ float to_tf32(float f) {
    unsigned u; asm("cvt.rna.tf32.f32 %0, %1;" : "=r"(u) : "f"(f));
    return __uint_as_float(u);
}
__device__ __forceinline__ float4 cvt4(float4 v) {
    return make_float4(to_tf32(v.x), to_tf32(v.y), to_tf32(v.z), to_tf32(v.w));
}

#define LDSM4(r0, r1, r2, r3, addr) \
    asm volatile("ldmatrix.sync.aligned.m8n8.x4.shared.b16 {%0,%1,%2,%3}, [%4];" \
                 : "=r"(r0), "=r"(r1), "=r"(r2), "=r"(r3) : "r"(addr))

#define MMA_TF32(d, a, b0, b1) \
    asm volatile("mma.sync.aligned.m16n8k8.row.col.f32.tf32.tf32.f32 " \
                 "{%0,%1,%2,%3}, {%4,%5,%6,%7}, {%8,%9}, {%0,%1,%2,%3};" \
                 : "+f"(d[0]), "+f"(d[1]), "+f"(d[2]), "+f"(d[3]) \
                 : "r"(a[0]), "r"(a[1]), "r"(a[2]), "r"(a[3]), "r"(b0), "r"(b1))

// ---------------- LayerNorm + fused fp32 dt_raw (one head per warp) ----------------
__global__ __launch_bounds__(256) void k_ln(const float* __restrict__ x,
                                            const float* __restrict__ gamma,
                                            const float* __restrict__ beta,
                                            const float* __restrict__ W) {
    int t = blockIdx.x, tid = threadIdx.x;
    int warp = tid >> 5, lane = tid & 31;
    float v = x[t * 256 + tid];
    float s = v, s2 = v * v;
    #pragma unroll
    for (int o = 16; o; o >>= 1) {
        s  += __shfl_xor_sync(0xffffffffu, s, o);
        s2 += __shfl_xor_sync(0xffffffffu, s2, o);
    }
    __shared__ float ws[8], ws2[8];
    if (lane == 0) { ws[warp] = s; ws2[warp] = s2; }
    __syncthreads();
    __shared__ float s_mu, s_rstd;
    if (tid == 0) {
        float a = 0.f, b = 0.f;
        #pragma unroll
        for (int i = 0; i < 8; i++) { a += ws[i]; b += ws2[i]; }
        float mu = a * (1.f / 256.f);
        float var = b * (1.f / 256.f) - mu * mu;
        s_mu = mu; s_rstd = rsqrtf(var + 1e-5f);
    }
    __syncthreads();
    float xn = (v - s_mu) * s_rstd * gamma[tid] + beta[tid];
    g_xn[t * 256 + tid] = xn;
    // fused dt_raw: warp w computes the fp32 dot for head h=w
    __shared__ float sxn[256];
    sxn[tid] = xn;
    __syncthreads();
    const float* w8 = W + (long)(1280 + warp) * 256;
    float d = 0.f;
    #pragma unroll
    for (int i = 0; i < 8; i++) {
        int k = lane + 32 * i;
        d += sxn[k] * w8[k];
    }
    #pragma unroll
    for (int o = 16; o; o >>= 1) d += __shfl_xor_sync(0xffffffffu, d, o);
    if (lane == 0) g_dtraw[t * 8 + warp] = d;
}

// ---------------- tf32 GEMM (double-buffered): C[M,N]=A[M,K]*B[N,K]^T, batched ----------------
__global__ __launch_bounds__(256) void k_gemm_tc(const float* __restrict__ A,
                                                 const float* __restrict__ B,
                                                 float* __restrict__ C,
                                                 int M, int N, int K,
                                                 long sA, long sB, long sC) {
    extern __shared__ float smg[];   // [A0|A1|B0|B1], 4608 floats each
    A += (long)blockIdx.z * sA;
    B += (long)blockIdx.z * sB;
    C += (long)blockIdx.z * sC;
    const int tid = threadIdx.x;
    const int warp = tid >> 5, lane = tid & 31;
    const int wm = (warp >> 1) * 32;
    const int wn = (warp & 1) * 64;
    const long m0 = (long)blockIdx.y * 128;
    const int n0 = blockIdx.x * 128;
    const int lr = tid >> 1;
    const int lc = tid & 1;
    const int lr16 = lane & 15;
    const int khalf = (lane >> 4) * 4;
    float acc[2][8][4] = {};
    const int ntiles = K >> 5;
    const bool nvalid = (n0 + lr) < N;
    const float* Arow = A + (m0 + lr) * K;
    const float* Brow = B + (long)(n0 + lr) * K;
    float4 va[4], vb[4];

    #pragma unroll
    for (int i = 0; i < 4; i++) {
        int cc = (lc + 2 * i) * 4;
        va[i] = *(const float4*)(Arow + cc);
        vb[i] = nvalid ? *(const float4*)(Brow + cc) : make_float4(0.f, 0.f, 0.f, 0.f);
    }
    #pragma unroll
    for (int i = 0; i < 4; i++) {
        int cc = (lc + 2 * i) * 4;
        *(float4*)&smg[lr * 36 + cc]        = cvt4(va[i]);
        *(float4*)&smg[9216 + lr * 36 + cc] = cvt4(vb[i]);
    }
    __syncthreads();

    for (int kt = 0; kt < ntiles; kt++) {
        if (kt + 1 < ntiles) {
            int k0 = (kt + 1) << 5;
            #pragma unroll
            for (int i = 0; i < 4; i++) {
                int cc = (lc + 2 * i) * 4;
                va[i] = *(const float4*)(Arow + k0 + cc);
                vb[i] = nvalid ? *(const float4*)(Brow + k0 + cc) : make_float4(0.f, 0.f, 0.f, 0.f);
            }
        }
        const unsigned sAb = (unsigned)__cvta_generic_to_shared(smg + (kt & 1) * 4608);
        const unsigned sBb = (unsigned)__cvta_generic_to_shared(smg + 9216 + (kt & 1) * 4608);
        #pragma unroll
        for (int kk = 0; kk < 32; kk += 8) {
            unsigned af[2][4];
            #pragma unroll
            for (int mt = 0; mt < 2; mt++) {
                unsigned ad = sAb + (unsigned)(((wm + mt * 16 + lr16) * 36 + kk + khalf) * 4);
                LDSM4(af[mt][0], af[mt][1], af[mt][2], af[mt][3], ad);
            }
            unsigned bf[4][4];
            #pragma unroll
            for (int nt = 0; nt < 4; nt++) {
                unsigned bd = sBb + (unsigned)(((wn + nt * 16 + lr16) * 36 + kk + khalf) * 4);
                LDSM4(bf[nt][0], bf[nt][1], bf[nt][2], bf[nt][3], bd);
            }
            #pragma unroll
            for (int mt = 0; mt < 2; mt++)
                #pragma unroll
                for (int nt = 0; nt < 4; nt++) {
                    MMA_TF32(acc[mt][nt * 2 + 0], af[mt], bf[nt][0], bf[nt][2]);
                    MMA_TF32(acc[mt][nt * 2 + 1], af[mt], bf[nt][1], bf[nt][3]);
                }
        }
        if (kt + 1 < ntiles) {
            float* dA = smg + ((kt + 1) & 1) * 4608;
            float* dB = smg + 9216 + ((kt + 1) & 1) * 4608;
            #pragma unroll
            for (int i = 0; i < 4; i++) {
                int cc = (lc + 2 * i) * 4;
                *(float4*)&dA[lr * 36 + cc] = cvt4(va[i]);
                *(float4*)&dB[lr * 36 + cc] = cvt4(vb[i]);
            }
            __syncthreads();
        }
    }
    const int g = lane >> 2, tq = lane & 3;
    #pragma unroll
    for (int mt = 0; mt < 2; mt++) {
        long m = m0 + wm + mt * 16 + g;
        #pragma unroll
        for (int j = 0; j < 8; j++) {
            int n = n0 + wn + j * 8 + 2 * tq;
            if (n < N) {
                *(float2*)&C[m * N + n]       = make_float2(acc[mt][j][0], acc[mt][j][1]);
                *(float2*)&C[(m + 8) * N + n] = make_float2(acc[mt][j][2], acc[mt][j][3]);
            }
        }
    }
}

// ---------------- tiled conv + SiLU + splits + dt/a (32-token tiles) ----------------
__global__ __launch_bounds__(256) void k_conv(const float* __restrict__ conv_w,
                                              const float* __restrict__ conv_b,
                                              const float* __restrict__ dt_bias,
                                              const float* __restrict__ A_log,
                                              const int* __restrict__ pts) {
    extern __shared__ float s_in[];          // 35 * 256
    __shared__ int s_v[32];
    int cx = blockIdx.x, tid = threadIdx.x;
    long t0 = (long)blockIdx.y * 32;
    int c0 = cx * 256;
    for (int i = tid; i < 35 * 64; i += 256) {
        int row = i >> 6, c4 = (i & 63) * 4;
        long t = t0 - 3 + row;
        float4 v = (t >= 0) ? *(const float4*)(g_zx + t * D_IN_PROJ + 512 + c0 + c4)
                            : make_float4(0.f, 0.f, 0.f, 0.f);
        *(float4*)&s_in[row * 256 + c4] = v;
    }
    if (tid < 32) {
        int t = (int)t0 + tid;
        int b = 0; bool s0 = false, s1 = false, s2 = false;
        #pragma unroll
        for (int j = 0; j < 8; j++) {
            if (b == t) s0 = true;
            if (b == t - 1) s1 = true;
            if (b == t - 2) s2 = true;
            b += pts[j];
        }
        bool v1 = !s0, v2 = v1 && !s1, v3 = v2 && !s2;
        s_v[tid] = (v1 ? 1 : 0) | (v2 ? 2 : 0) | (v3 ? 4 : 0) | (s0 ? 8 : 0);
    }
    __syncthreads();
    if (cx == 0) {
        int tok = tid >> 3, h = tid & 7;
        long t = t0 + tok;
        float xr = g_dtraw[t * 8 + h] + dt_bias[h];
        float dt = (xr > 20.f) ? xr : log1pf(expf(xr));
        g_dt[t * 8 + h] = dt;
        float a = -expf(A_log[h]) * dt;
        if (s_v[tok] & 8) a = NEGV;
        g_a[(((int)t >> 7) * 8 + h) * 128 + ((int)t & 127)] = a;
    }
    int ch = tid;
    float4 w = *(const float4*)(conv_w + (c0 + ch) * 4);
    float bias = conv_b[c0 + ch];
    #pragma unroll 4
    for (int tok = 0; tok < 32; tok++) {
        int m = s_v[tok];
        float acc = bias + s_in[(tok + 3) * 256 + ch] * w.w;
        if (m & 1) acc += s_in[(tok + 2) * 256 + ch] * w.z;
        if (m & 2) acc += s_in[(tok + 1) * 256 + ch] * w.y;
        if (m & 4) acc += s_in[(tok + 0) * 256 + ch] * w.x;
        float v = acc / (1.f + __expf(-acc));
        long t = t0 + tok;
        if (cx < 2) g_xh[t * 512 + c0 + ch] = v;
        else if (ch < 128) g_Bmat[t * 128 + ch] = v;
        else g_Cmat[t * 128 + (ch - 128)] = v;
    }
}

// ---------------- per-(chunk,head) cumsum of a ----------------
__global__ __launch_bounds__(256) void k_cumsum() {
    int idx = blockIdx.x * 8 + (threadIdx.x >> 5);
    int lane = threadIdx.x & 31;
    float4 v4 = *(const float4*)(g_a + idx * 128 + lane * 4);
    float p0 = v4.x, p1 = p0 + v4.y, p2 = p1 + v4.z, p3 = p2 + v4.w;
    float e = p3;
    #pragma unroll
    for (int o = 1; o < 32; o <<= 1) {
        float n = __shfl_up_sync(0xffffffffu, e, o);
        if (lane >= o) e += n;
    }
    float ex = e - p3;
    *(float4*)(g_Acum + idx * 128 + lane * 4) =
        make_float4(ex + p0, ex + p1, ex + p2, ex + p3);
    if (lane == 31) g_cd[idx] = expf(ex + p3);
}

// ---------------- k_chunk: Ydiag (+D*xh) and chunk_states via tf32 mma ----------------
__global__ __launch_bounds__(256) void k_chunk(const float* __restrict__ Dp) {
    extern __shared__ float sm[];
    float* sP   = sm;                   // 128 x 132
    float* sXT  = sm + 128 * 132;       // 64 x 132
    float* sAc  = sXT + 64 * 132;
    float* sDt  = sAc + 128;
    float* sDec = sDt + 128;
    int c = blockIdx.x, h = blockIdx.y, tid = threadIdx.x;
    int warp = tid >> 5, lane = tid & 31;
    int lr16 = lane & 15, khalf = (lane >> 4) * 4;
    const unsigned sPb = (unsigned)__cvta_generic_to_shared(sP);
    const unsigned sXb = (unsigned)__cvta_generic_to_shared(sXT);

    if (tid < 128) {
        sAc[tid] = g_Acum[(c * 8 + h) * 128 + tid];
        sDt[tid] = g_dt[((long)c * 128 + tid) * 8 + h];
    }
    __syncthreads();
    float alast = sAc[127];
    if (tid < 128) sDec[tid] = __expf(alast - sAc[tid]);
    const float* Xg = g_xh + (long)c * 128 * 512 + h * 64;
    for (int i = tid; i < 8192; i += 256) {
        int s = i >> 6, p = i & 63;
        sXT[p * 132 + s] = to_tf32(Xg[s * 512 + p] * sDt[s]);
    }
    const float* Mg = g_M + (long)c * 16384;
    for (int i = tid; i < 16384; i += 256) {
        int q = i >> 7, s = i & 127;
        sP[q * 132 + s] = (s <= q) ? to_tf32(Mg[i] * __expf(sAc[q] - sAc[s])) : 0.f;
    }
    __syncthreads();

    float acc[8][4] = {};
    int wm = warp * 16;
    for (int kk = 0; kk < 128; kk += 8) {
        unsigned af[4];
        unsigned ad = sPb + (unsigned)(((wm + lr16) * 132 + kk + khalf) * 4);
        LDSM4(af[0], af[1], af[2], af[3], ad);
        unsigned bf[4][4];
        #pragma unroll
        for (int nt = 0; nt < 4; nt++) {
            unsigned bd = sXb + (unsigned)(((nt * 16 + lr16) * 132 + kk + khalf) * 4);
            LDSM4(bf[nt][0], bf[nt][1], bf[nt][2], bf[nt][3], bd);
        }
        #pragma unroll
        for (int nt = 0; nt < 4; nt++) {
            MMA_TF32(acc[nt * 2 + 0], af, bf[nt][0], bf[nt][2]);
            MMA_TF32(acc[nt * 2 + 1], af, bf[nt][1], bf[nt][3]);
        }
    }
    float Dh = Dp[h];
    int g = lane >> 2, tq = lane & 3;
    {
        long r0 = ((long)c * 128 + wm + g) * 512 + h * 64;
        long r1 = r0 + 8 * 512;
        #pragma unroll
        for (int j = 0; j < 8; j++) {
            int n = j * 8 + 2 * tq;
            float2 x0 = *(const float2*)&g_xh[r0 + n];
            float2 x1 = *(const float2*)&g_xh[r1 + n];
            *(float2*)&g_y[r0 + n] = make_float2(acc[j][0] + Dh * x0.x, acc[j][1] + Dh * x0.y);
            *(float2*)&g_y[r1 + n] = make_float2(acc[j][2] + Dh * x1.x, acc[j][3] + Dh * x1.y);
        }
    }
    __syncthreads();

    for (int i = tid; i < 8192; i += 256) {
        int p = i >> 7, s = i & 127;
        sXT[p * 132 + s] = to_tf32(sXT[p * 132 + s] * sDec[s]);
    }
    const float* Bg = g_Bmat + (long)c * 16384;
    for (int i = tid; i < 16384; i += 256) {
        int s = i >> 7, n = i & 127;
        sP[n * 132 + s] = to_tf32(Bg[i]);
    }
    __syncthreads();

    float acc2[8][4] = {};
    int wm2 = (warp & 3) * 16, wn2 = (warp >> 2) * 64;
    for (int kk = 0; kk < 128; kk += 8) {
        unsigned af[4];
        unsigned ad = sXb + (unsigned)(((wm2 + lr16) * 132 + kk + khalf) * 4);
        LDSM4(af[0], af[1], af[2], af[3], ad);
        unsigned bf[4][4];
        #pragma unroll
        for (int nt = 0; nt < 4; nt++) {
            unsigned bd = sPb + (unsigned)(((wn2 + nt * 16 + lr16) * 132 + kk + khalf) * 4);
            LDSM4(bf[nt][0], bf[nt][1], bf[nt][2], bf[nt][3], bd);
        }
        #pragma unroll
        for (int nt = 0; nt < 4; nt++) {
            MMA_TF32(acc2[nt * 2 + 0], af, bf[nt][0], bf[nt][2]);
            MMA_TF32(acc2[nt * 2 + 1], af, bf[nt][1], bf[nt][3]);
        }
    }
    float* So = g_cs + ((long)c * 8 + h) * 8192;
    #pragma unroll
    for (int j = 0; j < 8; j++) {
        int n = wn2 + j * 8 + 2 * tq;
        int p = wm2 + g;
        *(float2*)&So[p * 128 + n]       = make_float2(acc2[j][0], acc2[j][1]);
        *(float2*)&So[(p + 8) * 128 + n] = make_float2(acc2[j][2], acc2[j][3]);
    }
}

// ---------------- inter-chunk scan ----------------
__global__ __launch_bounds__(256) void k_scan() {
    int e = blockIdx.x * 256 + threadIdx.x;
    int h = e >> 13;
    float st = 0.f;
    const float* cdp = g_cd + h;
    for (int c = 0; c < NCHUNK; c++) {
        g_ps[c * 65536 + e] = st;
        st = st * cdp[c * 8] + g_cs[c * 65536 + e];
    }
}

// ---------------- k_yoff via tf32 mma ----------------
__global__ __launch_bounds__(256) void k_yoff() {
    extern __shared__ float sm[];
    float* sC  = sm;                    // 128 x 132
    float* sPS = sm + 128 * 132;        // 64 x 132
    float* sAc = sPS + 64 * 132;
    int c = blockIdx.x, h = blockIdx.y, tid = threadIdx.x;
    int warp = tid >> 5, lane = tid & 31;
    int lr16 = lane & 15, khalf = (lane >> 4) * 4;
    const unsigned sCb = (unsigned)__cvta_generic_to_shared(sC);
    const unsigned sSb = (unsigned)__cvta_generic_to_shared(sPS);

    if (tid < 128) sAc[tid] = g_Acum[(c * 8 + h) * 128 + tid];
    const float* Cg = g_Cmat + (long)c * 16384;
    for (int i = tid; i < 16384; i += 256) {
        int q = i >> 7, n = i & 127;
        sC[q * 132 + n] = to_tf32(Cg[i]);
    }
    const float* Pg = g_ps + ((long)c * 8 + h) * 8192;
    for (int i = tid; i < 8192; i += 256) {
        int p = i >> 7, n = i & 127;
        sPS[p * 132 + n] = to_tf32(Pg[i]);
    }
    __syncthreads();

    float acc[8][4] = {};
    int wm = warp * 16;
    for (int kk = 0; kk < 128; kk += 8) {
        unsigned af[4];
        unsigned ad = sCb + (unsigned)(((wm + lr16) * 132 + kk + khalf) * 4);
        LDSM4(af[0], af[1], af[2], af[3], ad);
        unsigned bf[4][4];
        #pragma unroll
        for (int nt = 0; nt < 4; nt++) {
            unsigned bd = sSb + (unsigned)(((nt * 16 + lr16) * 132 + kk + khalf) * 4);
            LDSM4(bf[nt][0], bf[nt][1], bf[nt][2], bf[nt][3], bd);
        }
        #pragma unroll
        for (int nt = 0; nt < 4; nt++) {
            MMA_TF32(acc[nt * 2 + 0], af, bf[nt][0], bf[nt][2]);
            MMA_TF32(acc[nt * 2 + 1], af, bf[nt][1], bf[nt][3]);
        }
    }
    int g = lane >> 2, tq = lane & 3;
    float eq0 = __expf(sAc[wm + g]);
    float eq1 = __expf(sAc[wm + g + 8]);
    long r0 = ((long)c * 128 + wm + g) * 512 + h * 64;
    long r1 = r0 + 8 * 512;
    #pragma unroll
    for (int j = 0; j < 8; j++) {
        int n = j * 8 + 2 * tq;
        float2 y0 = *(const float2*)&g_y[r0 + n];
        float2 y1 = *(const float2*)&g_y[r1 + n];
        *(float2*)&g_y[r0 + n] = make_float2(y0.x + eq0 * acc[j][0], y0.y + eq0 * acc[j][1]);
        *(float2*)&g_y[r1 + n] = make_float2(y1.x + eq1 * acc[j][2], y1.y + eq1 * acc[j][3]);
    }
}

// ---------------- gated RMSNorm ----------------
__global__ __launch_bounds__(256) void k_gate(const float* __restrict__ norm_w) {
    int t = blockIdx.x, tid = threadIdx.x;
    float y0 = g_y[t * 512 + tid];
    float z0 = g_zx[(long)t * D_IN_PROJ + tid];
    float gv0 = y0 * (z0 / (1.f + __expf(-z0)));
    float y1 = g_y[t * 512 + tid + 256];
    float z1 = g_zx[(long)t * D_IN_PROJ + tid + 256];
    float gv1 = y1 * (z1 / (1.f + __expf(-z1)));
    float ss = gv0 * gv0 + gv1 * gv1;
    #pragma unroll
    for (int o = 16; o; o >>= 1) ss += __shfl_xor_sync(0xffffffffu, ss, o);
    __shared__ float ws[8];
    if ((tid & 31) == 0) ws[tid >> 5] = ss;
    __syncthreads();
    __shared__ float s_scale;
    if (tid == 0) {
        float a = 0.f;
        #pragma unroll
        for (int i = 0; i < 8; i++) a += ws[i];
        s_scale = rsqrtf(a * (1.f / 512.f) + 1e-5f);
    }
    __syncthreads();
    g_g[t * 512 + tid]       = gv0 * s_scale * norm_w[tid];
    g_g[t * 512 + tid + 256] = gv1 * s_scale * norm_w[tid + 256];
}

// ---------------- launch ----------------
extern "C" void kernel_launch(void* const* d_in, const int* in_sizes, int n_in,
                              void* d_out, int out_size) {
    const float* x         = (const float*)d_in[0];
    const float* ln_gamma  = (const float*)d_in[1];
    const float* ln_beta   = (const float*)d_in[2];
    const float* in_proj_w = (const float*)d_in[3];
    const float* conv_w    = (const float*)d_in[4];
    const float* conv_b    = (const float*)d_in[5];
    const float* dt_bias   = (const float*)d_in[6];
    const float* A_log     = (const float*)d_in[7];
    const float* Dv        = (const float*)d_in[8];
    const float* norm_w    = (const float*)d_in[9];
    const float* out_proj_w= (const float*)d_in[10];
    const int*   pts       = (const int*)d_in[11];
    float* out = (float*)d_out;

    const int SMEM_GEMM  = 4 * 4608 * 4;                               // 73728
    const int SMEM_CONV  = 35 * 256 * 4;                               // 35840
    const int SMEM_CHUNK = (128 * 132 + 64 * 132 + 384) * 4;
    const int SMEM_YOFF  = (128 * 132 + 64 * 132 + 128) * 4;
    cudaFuncSetAttribute(k_gemm_tc, cudaFuncAttributeMaxDynamicSharedMemorySize, SMEM_GEMM);
    cudaFuncSetAttribute(k_conv,  cudaFuncAttributeMaxDynamicSharedMemorySize, SMEM_CONV);
    cudaFuncSetAttribute(k_chunk, cudaFuncAttributeMaxDynamicSharedMemorySize, SMEM_CHUNK);
    cudaFuncSetAttribute(k_yoff,  cudaFuncAttributeMaxDynamicSharedMemorySize, SMEM_YOFF);

    float *p_xn, *p_zx, *p_B, *p_C, *p_M, *p_g;
    cudaGetSymbolAddress((void**)&p_xn, g_xn);
    cudaGetSymbolAddress((void**)&p_zx, g_zx);
    cudaGetSymbolAddress((void**)&p_B,  g_Bmat);
    cudaGetSymbolAddress((void**)&p_C,  g_Cmat);
    cudaGetSymbolAddress((void**)&p_M,  g_M);
    cudaGetSymbolAddress((void**)&p_g,  g_g);

    k_ln<<<T_TOTAL, 256>>>(x, ln_gamma, ln_beta, in_proj_w);
    k_gemm_tc<<<dim3(11, 512, 1), 256, SMEM_GEMM>>>(p_xn, in_proj_w, p_zx,
                                                    T_TOTAL, D_IN_PROJ, D_MODEL, 0, 0, 0);
    k_conv<<<dim3(3, 2048), 256, SMEM_CONV>>>(conv_w, conv_b, dt_bias, A_log, pts);
    k_cumsum<<<512, 256>>>();
    k_gemm_tc<<<dim3(1, 1, 512), 256, SMEM_GEMM>>>(p_C, p_B, p_M,
                                                   128, 128, 128, 16384, 16384, 16384);
    k_chunk<<<dim3(512, 8), 256, SMEM_CHUNK>>>(Dv);
    k_scan<<<256, 256>>>();
    k_yoff<<<dim3(512, 8), 256, SMEM_YOFF>>>();
    k_gate<<<T_TOTAL, 256>>>(norm_w);
    k_gemm_tc<<<dim3(2, 512, 1), 256, SMEM_GEMM>>>(p_g, out_proj_w, out,
                                                   T_TOTAL, D_MODEL, D_INNER, 0, 0, 0);
}

// round 12
// speedup vs baseline: 1.2675x; 1.0795x over previous
#include <cuda_runtime.h>
#include <cuda_bf16.h>
#include <stdint.h>
#include <math.h>

#define T_TOTAL 65536
#define D_MODEL 256
#define D_INNER 512
#define HEADDIM 64
#define NHEADS 8
#define DSTATE 128
#define CHUNK 128
#define CONV_DIM 768
#define D_IN_PROJ 1288
#define NCHUNK 512
#define NEGV -10000.0f

// ---------------- scratch ----------------
static __device__ float g_xn[T_TOTAL * D_MODEL];
static __device__ float g_zx[T_TOTAL * D_IN_PROJ];
static __device__ float g_dtraw[T_TOTAL * NHEADS];
static __device__ float g_dt[T_TOTAL * NHEADS];
static __device__ float g_xh[T_TOTAL * D_INNER];
static __device__ float g_Bmat[T_TOTAL * DSTATE];
static __device__ float g_Cmat[T_TOTAL * DSTATE];
static __device__ float g_a[T_TOTAL * NHEADS];
static __device__ float g_Acum[T_TOTAL * NHEADS];
static __device__ float g_cd[NCHUNK * NHEADS];
static __device__ float g_M[NCHUNK * CHUNK * CHUNK];
static __device__ float g_cs[NCHUNK * NHEADS * HEADDIM * DSTATE];
static __device__ float g_ps[NCHUNK * NHEADS * HEADDIM * DSTATE];
static __device__ float g_y[T_TOTAL * D_INNER];
static __device__ float g_g[T_TOTAL * D_INNER];

// ---------------- helpers ----------------
__device__ __forceinline__ float to_tf32(float f) {
    unsigned u; asm("cvt.rna.tf32.f32 %0, %1;" : "=r"(u) : "f"(f));
    return __uint_as_float(u);
}
__device__ __forceinline__ float4 cvt4(float4 v) {
    return make_float4(to_tf32(v.x), to_tf32(v.y), to_tf32(v.z), to_tf32(v.w));
}

#define LDSM4(r0, r1, r2, r3, addr) \
    asm volatile("ldmatrix.sync.aligned.m8n8.x4.shared.b16 {%0,%1,%2,%3}, [%4];" \
                 : "=r"(r0), "=r"(r1), "=r"(r2), "=r"(r3) : "r"(addr))

#define MMA_TF32(d, a, b0, b1) \
    asm volatile("mma.sync.aligned.m16n8k8.row.col.f32.tf32.tf32.f32 " \
                 "{%0,%1,%2,%3}, {%4,%5,%6,%7}, {%8,%9}, {%0,%1,%2,%3};" \
                 : "+f"(d[0]), "+f"(d[1]), "+f"(d[2]), "+f"(d[3]) \
                 : "r"(a[0]), "r"(a[1]), "r"(a[2]), "r"(a[3]), "r"(b0), "r"(b1))

// ---------------- LayerNorm + fused fp32 dt_raw (one head per warp) ----------------
__global__ __launch_bounds__(256) void k_ln(const float* __restrict__ x,
                                            const float* __restrict__ gamma,
                                            const float* __restrict__ beta,
                                            const float* __restrict__ W) {
    int t = blockIdx.x, tid = threadIdx.x;
    int warp = tid >> 5, lane = tid & 31;
    float v = x[t * 256 + tid];
    float s = v, s2 = v * v;
    #pragma unroll
    for (int o = 16; o; o >>= 1) {
        s  += __shfl_xor_sync(0xffffffffu, s, o);
        s2 += __shfl_xor_sync(0xffffffffu, s2, o);
    }
    __shared__ float ws[8], ws2[8];
    if (lane == 0) { ws[warp] = s; ws2[warp] = s2; }
    __syncthreads();
    __shared__ float s_mu, s_rstd;
    if (tid == 0) {
        float a = 0.f, b = 0.f;
        #pragma unroll
        for (int i = 0; i < 8; i++) { a += ws[i]; b += ws2[i]; }
        float mu = a * (1.f / 256.f);
        float var = b * (1.f / 256.f) - mu * mu;
        s_mu = mu; s_rstd = rsqrtf(var + 1e-5f);
    }
    __syncthreads();
    float xn = (v - s_mu) * s_rstd * gamma[tid] + beta[tid];
    g_xn[t * 256 + tid] = xn;
    __shared__ float sxn[256];
    sxn[tid] = xn;
    __syncthreads();
    const float* w8 = W + (long)(1280 + warp) * 256;
    float d = 0.f;
    #pragma unroll
    for (int i = 0; i < 8; i++) {
        int k = lane + 32 * i;
        d += sxn[k] * w8[k];
    }
    #pragma unroll
    for (int o = 16; o; o >>= 1) d += __shfl_xor_sync(0xffffffffu, d, o);
    if (lane == 0) g_dtraw[t * 8 + warp] = d;
}

// ---------------- tf32 GEMM (double-buffered): C[M,N]=A[M,K]*B[N,K]^T, batched ----------------
// tri=1: skip warps whose whole output tile is strictly above the diagonal (M-GEMM only).
__global__ __launch_bounds__(256) void k_gemm_tc(const float* __restrict__ A,
                                                 const float* __restrict__ B,
                                                 float* __restrict__ C,
                                                 int M, int N, int K,
                                                 long sA, long sB, long sC, int tri) {
    extern __shared__ float smg[];   // [A0|A1|B0|B1], 4608 floats each
    A += (long)blockIdx.z * sA;
    B += (long)blockIdx.z * sB;
    C += (long)blockIdx.z * sC;
    const int tid = threadIdx.x;
    const int warp = tid >> 5, lane = tid & 31;
    const int wm = (warp >> 1) * 32;
    const int wn = (warp & 1) * 64;
    const long m0 = (long)blockIdx.y * 128;
    const int n0 = blockIdx.x * 128;
    const int lr = tid >> 1;
    const int lc = tid & 1;
    const int lr16 = lane & 15;
    const int khalf = (lane >> 4) * 4;
    float acc[2][8][4] = {};
    const int ntiles = K >> 5;
    const bool nvalid = (n0 + lr) < N;
    const bool skipw = tri && (wn >= wm + 32);
    const float* Arow = A + (m0 + lr) * K;
    const float* Brow = B + (long)(n0 + lr) * K;
    float4 va[4], vb[4];

    #pragma unroll
    for (int i = 0; i < 4; i++) {
        int cc = (lc + 2 * i) * 4;
        va[i] = *(const float4*)(Arow + cc);
        vb[i] = nvalid ? *(const float4*)(Brow + cc) : make_float4(0.f, 0.f, 0.f, 0.f);
    }
    #pragma unroll
    for (int i = 0; i < 4; i++) {
        int cc = (lc + 2 * i) * 4;
        *(float4*)&smg[lr * 36 + cc]        = cvt4(va[i]);
        *(float4*)&smg[9216 + lr * 36 + cc] = cvt4(vb[i]);
    }
    __syncthreads();

    for (int kt = 0; kt < ntiles; kt++) {
        if (kt + 1 < ntiles) {
            int k0 = (kt + 1) << 5;
            #pragma unroll
            for (int i = 0; i < 4; i++) {
                int cc = (lc + 2 * i) * 4;
                va[i] = *(const float4*)(Arow + k0 + cc);
                vb[i] = nvalid ? *(const float4*)(Brow + k0 + cc) : make_float4(0.f, 0.f, 0.f, 0.f);
            }
        }
        if (!skipw) {
            const unsigned sAb = (unsigned)__cvta_generic_to_shared(smg + (kt & 1) * 4608);
            const unsigned sBb = (unsigned)__cvta_generic_to_shared(smg + 9216 + (kt & 1) * 4608);
            #pragma unroll
            for (int kk = 0; kk < 32; kk += 8) {
                unsigned af[2][4];
                #pragma unroll
                for (int mt = 0; mt < 2; mt++) {
                    unsigned ad = sAb + (unsigned)(((wm + mt * 16 + lr16) * 36 + kk + khalf) * 4);
                    LDSM4(af[mt][0], af[mt][1], af[mt][2], af[mt][3], ad);
                }
                unsigned bf[4][4];
                #pragma unroll
                for (int nt = 0; nt < 4; nt++) {
                    unsigned bd = sBb + (unsigned)(((wn + nt * 16 + lr16) * 36 + kk + khalf) * 4);
                    LDSM4(bf[nt][0], bf[nt][1], bf[nt][2], bf[nt][3], bd);
                }
                #pragma unroll
                for (int mt = 0; mt < 2; mt++)
                    #pragma unroll
                    for (int nt = 0; nt < 4; nt++) {
                        MMA_TF32(acc[mt][nt * 2 + 0], af[mt], bf[nt][0], bf[nt][2]);
                        MMA_TF32(acc[mt][nt * 2 + 1], af[mt], bf[nt][1], bf[nt][3]);
                    }
            }
        }
        if (kt + 1 < ntiles) {
            float* dA = smg + ((kt + 1) & 1) * 4608;
            float* dB = smg + 9216 + ((kt + 1) & 1) * 4608;
            #pragma unroll
            for (int i = 0; i < 4; i++) {
                int cc = (lc + 2 * i) * 4;
                *(float4*)&dA[lr * 36 + cc] = cvt4(va[i]);
                *(float4*)&dB[lr * 36 + cc] = cvt4(vb[i]);
            }
            __syncthreads();
        }
    }
    if (skipw) return;
    const int g = lane >> 2, tq = lane & 3;
    #pragma unroll
    for (int mt = 0; mt < 2; mt++) {
        long m = m0 + wm + mt * 16 + g;
        #pragma unroll
        for (int j = 0; j < 8; j++) {
            int n = n0 + wn + j * 8 + 2 * tq;
            if (n < N) {
                *(float2*)&C[m * N + n]       = make_float2(acc[mt][j][0], acc[mt][j][1]);
                *(float2*)&C[(m + 8) * N + n] = make_float2(acc[mt][j][2], acc[mt][j][3]);
            }
        }
    }
}

// ---------------- tiled conv + SiLU + splits + dt/a (32-token tiles) ----------------
__global__ __launch_bounds__(256) void k_conv(const float* __restrict__ conv_w,
                                              const float* __restrict__ conv_b,
                                              const float* __restrict__ dt_bias,
                                              const float* __restrict__ A_log,
                                              const int* __restrict__ pts) {
    extern __shared__ float s_in[];          // 35 * 256
    __shared__ int s_v[32];
    int cx = blockIdx.x, tid = threadIdx.x;
    long t0 = (long)blockIdx.y * 32;
    int c0 = cx * 256;
    for (int i = tid; i < 35 * 64; i += 256) {
        int row = i >> 6, c4 = (i & 63) * 4;
        long t = t0 - 3 + row;
        float4 v = (t >= 0) ? *(const float4*)(g_zx + t * D_IN_PROJ + 512 + c0 + c4)
                            : make_float4(0.f, 0.f, 0.f, 0.f);
        *(float4*)&s_in[row * 256 + c4] = v;
    }
    if (tid < 32) {
        int t = (int)t0 + tid;
        int b = 0; bool s0 = false, s1 = false, s2 = false;
        #pragma unroll
        for (int j = 0; j < 8; j++) {
            if (b == t) s0 = true;
            if (b == t - 1) s1 = true;
            if (b == t - 2) s2 = true;
            b += pts[j];
        }
        bool v1 = !s0, v2 = v1 && !s1, v3 = v2 && !s2;
        s_v[tid] = (v1 ? 1 : 0) | (v2 ? 2 : 0) | (v3 ? 4 : 0) | (s0 ? 8 : 0);
    }
    __syncthreads();
    if (cx == 0) {
        int tok = tid >> 3, h = tid & 7;
        long t = t0 + tok;
        float xr = g_dtraw[t * 8 + h] + dt_bias[h];
        float dt = (xr > 20.f) ? xr : log1pf(expf(xr));
        g_dt[t * 8 + h] = dt;
        float a = -expf(A_log[h]) * dt;
        if (s_v[tok] & 8) a = NEGV;
        g_a[(((int)t >> 7) * 8 + h) * 128 + ((int)t & 127)] = a;
    }
    int ch = tid;
    float4 w = *(const float4*)(conv_w + (c0 + ch) * 4);
    float bias = conv_b[c0 + ch];
    #pragma unroll 4
    for (int tok = 0; tok < 32; tok++) {
        int m = s_v[tok];
        float acc = bias + s_in[(tok + 3) * 256 + ch] * w.w;
        if (m & 1) acc += s_in[(tok + 2) * 256 + ch] * w.z;
        if (m & 2) acc += s_in[(tok + 1) * 256 + ch] * w.y;
        if (m & 4) acc += s_in[(tok + 0) * 256 + ch] * w.x;
        float v = acc / (1.f + __expf(-acc));
        long t = t0 + tok;
        if (cx < 2) g_xh[t * 512 + c0 + ch] = v;
        else if (ch < 128) g_Bmat[t * 128 + ch] = v;
        else g_Cmat[t * 128 + (ch - 128)] = v;
    }
}

// ---------------- per-(chunk,head) cumsum of a ----------------
__global__ __launch_bounds__(256) void k_cumsum() {
    int idx = blockIdx.x * 8 + (threadIdx.x >> 5);
    int lane = threadIdx.x & 31;
    float4 v4 = *(const float4*)(g_a + idx * 128 + lane * 4);
    float p0 = v4.x, p1 = p0 + v4.y, p2 = p1 + v4.z, p3 = p2 + v4.w;
    float e = p3;
    #pragma unroll
    for (int o = 1; o < 32; o <<= 1) {
        float n = __shfl_up_sync(0xffffffffu, e, o);
        if (lane >= o) e += n;
    }
    float ex = e - p3;
    *(float4*)(g_Acum + idx * 128 + lane * 4) =
        make_float4(ex + p0, ex + p1, ex + p2, ex + p3);
    if (lane == 31) g_cd[idx] = expf(ex + p3);
}

// ---------------- k_chunk: Ydiag (+D*xh) and chunk_states via tf32 mma ----------------
__global__ __launch_bounds__(256) void k_chunk(const float* __restrict__ Dp) {
    extern __shared__ float sm[];
    float* sP   = sm;                   // 128 x 132
    float* sXT  = sm + 128 * 132;       // 64 x 132
    float* sAc  = sXT + 64 * 132;
    float* sDt  = sAc + 128;
    float* sDec = sDt + 128;
    int c = blockIdx.x, h = blockIdx.y, tid = threadIdx.x;
    int warp = tid >> 5, lane = tid & 31;
    int lr16 = lane & 15, khalf = (lane >> 4) * 4;
    const unsigned sPb = (unsigned)__cvta_generic_to_shared(sP);
    const unsigned sXb = (unsigned)__cvta_generic_to_shared(sXT);

    if (tid < 128) {
        sAc[tid] = g_Acum[(c * 8 + h) * 128 + tid];
        sDt[tid] = g_dt[((long)c * 128 + tid) * 8 + h];
    }
    __syncthreads();
    float alast = sAc[127];
    if (tid < 128) sDec[tid] = __expf(alast - sAc[tid]);
    const float* Xg = g_xh + (long)c * 128 * 512 + h * 64;
    for (int i = tid; i < 8192; i += 256) {
        int s = i >> 6, p = i & 63;
        sXT[p * 132 + s] = to_tf32(Xg[s * 512 + p] * sDt[s]);
    }
    const float* Mg = g_M + (long)c * 16384;
    for (int i = tid; i < 16384; i += 256) {
        int q = i >> 7, s = i & 127;
        sP[q * 132 + s] = (s <= q) ? to_tf32(Mg[i] * __expf(sAc[q] - sAc[s])) : 0.f;
    }
    __syncthreads();

    // phase 1: Ydiag = P @ X ; P[q][s]=0 for s>q  =>  kk only up to wm+16
    float acc[8][4] = {};
    int wm = warp * 16;
    for (int kk = 0; kk < wm + 16; kk += 8) {
        unsigned af[4];
        unsigned ad = sPb + (unsigned)(((wm + lr16) * 132 + kk + khalf) * 4);
        LDSM4(af[0], af[1], af[2], af[3], ad);
        unsigned bf[4][4];
        #pragma unroll
        for (int nt = 0; nt < 4; nt++) {
            unsigned bd = sXb + (unsigned)(((nt * 16 + lr16) * 132 + kk + khalf) * 4);
            LDSM4(bf[nt][0], bf[nt][1], bf[nt][2], bf[nt][3], bd);
        }
        #pragma unroll
        for (int nt = 0; nt < 4; nt++) {
            MMA_TF32(acc[nt * 2 + 0], af, bf[nt][0], bf[nt][2]);
            MMA_TF32(acc[nt * 2 + 1], af, bf[nt][1], bf[nt][3]);
        }
    }
    float Dh = Dp[h];
    int g = lane >> 2, tq = lane & 3;
    {
        long r0 = ((long)c * 128 + wm + g) * 512 + h * 64;
        long r1 = r0 + 8 * 512;
        #pragma unroll
        for (int j = 0; j < 8; j++) {
            int n = j * 8 + 2 * tq;
            float2 x0 = *(const float2*)&g_xh[r0 + n];
            float2 x1 = *(const float2*)&g_xh[r1 + n];
            *(float2*)&g_y[r0 + n] = make_float2(acc[j][0] + Dh * x0.x, acc[j][1] + Dh * x0.y);
            *(float2*)&g_y[r1 + n] = make_float2(acc[j][2] + Dh * x1.x, acc[j][3] + Dh * x1.y);
        }
    }
    __syncthreads();

    for (int i = tid; i < 8192; i += 256) {
        int p = i >> 7, s = i & 127;
        sXT[p * 132 + s] = to_tf32(sXT[p * 132 + s] * sDec[s]);
    }
    const float* Bg = g_Bmat + (long)c * 16384;
    for (int i = tid; i < 16384; i += 256) {
        int s = i >> 7, n = i & 127;
        sP[n * 132 + s] = to_tf32(Bg[i]);
    }
    __syncthreads();

    float acc2[8][4] = {};
    int wm2 = (warp & 3) * 16, wn2 = (warp >> 2) * 64;
    for (int kk = 0; kk < 128; kk += 8) {
        unsigned af[4];
        unsigned ad = sXb + (unsigned)(((wm2 + lr16) * 132 + kk + khalf) * 4);
        LDSM4(af[0], af[1], af[2], af[3], ad);
        unsigned bf[4][4];
        #pragma unroll
        for (int nt = 0; nt < 4; nt++) {
            unsigned bd = sPb + (unsigned)(((wn2 + nt * 16 + lr16) * 132 + kk + khalf) * 4);
            LDSM4(bf[nt][0], bf[nt][1], bf[nt][2], bf[nt][3], bd);
        }
        #pragma unroll
        for (int nt = 0; nt < 4; nt++) {
            MMA_TF32(acc2[nt * 2 + 0], af, bf[nt][0], bf[nt][2]);
            MMA_TF32(acc2[nt * 2 + 1], af, bf[nt][1], bf[nt][3]);
        }
    }
    float* So = g_cs + ((long)c * 8 + h) * 8192;
    #pragma unroll
    for (int j = 0; j < 8; j++) {
        int n = wn2 + j * 8 + 2 * tq;
        int p = wm2 + g;
        *(float2*)&So[p * 128 + n]       = make_float2(acc2[j][0], acc2[j][1]);
        *(float2*)&So[(p + 8) * 128 + n] = make_float2(acc2[j][2], acc2[j][3]);
    }
}

// ---------------- inter-chunk scan (4-deep load prefetch) ----------------
__global__ __launch_bounds__(256) void k_scan() {
    int e = blockIdx.x * 256 + threadIdx.x;
    int h = e >> 13;
    float st = 0.f;
    const float* cdp = g_cd + h;
    const float* csp = g_cs + e;
    float* psp = g_ps + e;
    for (int c = 0; c < NCHUNK; c += 4) {
        float cs0 = csp[(long)(c + 0) * 65536];
        float cs1 = csp[(long)(c + 1) * 65536];
        float cs2 = csp[(long)(c + 2) * 65536];
        float cs3 = csp[(long)(c + 3) * 65536];
        float cd0 = cdp[(c + 0) * 8];
        float cd1 = cdp[(c + 1) * 8];
        float cd2 = cdp[(c + 2) * 8];
        float cd3 = cdp[(c + 3) * 8];
        psp[(long)(c + 0) * 65536] = st; st = st * cd0 + cs0;
        psp[(long)(c + 1) * 65536] = st; st = st * cd1 + cs1;
        psp[(long)(c + 2) * 65536] = st; st = st * cd2 + cs2;
        psp[(long)(c + 3) * 65536] = st; st = st * cd3 + cs3;
    }
}

// ---------------- k_yoff via tf32 mma ----------------
__global__ __launch_bounds__(256) void k_yoff() {
    extern __shared__ float sm[];
    float* sC  = sm;                    // 128 x 132
    float* sPS = sm + 128 * 132;        // 64 x 132
    float* sAc = sPS + 64 * 132;
    int c = blockIdx.x, h = blockIdx.y, tid = threadIdx.x;
    int warp = tid >> 5, lane = tid & 31;
    int lr16 = lane & 15, khalf = (lane >> 4) * 4;
    const unsigned sCb = (unsigned)__cvta_generic_to_shared(sC);
    const unsigned sSb = (unsigned)__cvta_generic_to_shared(sPS);

    if (tid < 128) sAc[tid] = g_Acum[(c * 8 + h) * 128 + tid];
    const float* Cg = g_Cmat + (long)c * 16384;
    for (int i = tid; i < 16384; i += 256) {
        int q = i >> 7, n = i & 127;
        sC[q * 132 + n] = to_tf32(Cg[i]);
    }
    const float* Pg = g_ps + ((long)c * 8 + h) * 8192;
    for (int i = tid; i < 8192; i += 256) {
        int p = i >> 7, n = i & 127;
        sPS[p * 132 + n] = to_tf32(Pg[i]);
    }
    __syncthreads();

    float acc[8][4] = {};
    int wm = warp * 16;
    for (int kk = 0; kk < 128; kk += 8) {
        unsigned af[4];
        unsigned ad = sCb + (unsigned)(((wm + lr16) * 132 + kk + khalf) * 4);
        LDSM4(af[0], af[1], af[2], af[3], ad);
        unsigned bf[4][4];
        #pragma unroll
        for (int nt = 0; nt < 4; nt++) {
            unsigned bd = sSb + (unsigned)(((nt * 16 + lr16) * 132 + kk + khalf) * 4);
            LDSM4(bf[nt][0], bf[nt][1], bf[nt][2], bf[nt][3], bd);
        }
        #pragma unroll
        for (int nt = 0; nt < 4; nt++) {
            MMA_TF32(acc[nt * 2 + 0], af, bf[nt][0], bf[nt][2]);
            MMA_TF32(acc[nt * 2 + 1], af, bf[nt][1], bf[nt][3]);
        }
    }
    int g = lane >> 2, tq = lane & 3;
    float eq0 = __expf(sAc[wm + g]);
    float eq1 = __expf(sAc[wm + g + 8]);
    long r0 = ((long)c * 128 + wm + g) * 512 + h * 64;
    long r1 = r0 + 8 * 512;
    #pragma unroll
    for (int j = 0; j < 8; j++) {
        int n = j * 8 + 2 * tq;
        float2 y0 = *(const float2*)&g_y[r0 + n];
        float2 y1 = *(const float2*)&g_y[r1 + n];
        *(float2*)&g_y[r0 + n] = make_float2(y0.x + eq0 * acc[j][0], y0.y + eq0 * acc[j][1]);
        *(float2*)&g_y[r1 + n] = make_float2(y1.x + eq1 * acc[j][2], y1.y + eq1 * acc[j][3]);
    }
}

// ---------------- gated RMSNorm ----------------
__global__ __launch_bounds__(256) void k_gate(const float* __restrict__ norm_w) {
    int t = blockIdx.x, tid = threadIdx.x;
    float y0 = g_y[t * 512 + tid];
    float z0 = g_zx[(long)t * D_IN_PROJ + tid];
    float gv0 = y0 * (z0 / (1.f + __expf(-z0)));
    float y1 = g_y[t * 512 + tid + 256];
    float z1 = g_zx[(long)t * D_IN_PROJ + tid + 256];
    float gv1 = y1 * (z1 / (1.f + __expf(-z1)));
    float ss = gv0 * gv0 + gv1 * gv1;
    #pragma unroll
    for (int o = 16; o; o >>= 1) ss += __shfl_xor_sync(0xffffffffu, ss, o);
    __shared__ float ws[8];
    if ((tid & 31) == 0) ws[tid >> 5] = ss;
    __syncthreads();
    __shared__ float s_scale;
    if (tid == 0) {
        float a = 0.f;
        #pragma unroll
        for (int i = 0; i < 8; i++) a += ws[i];
        s_scale = rsqrtf(a * (1.f / 512.f) + 1e-5f);
    }
    __syncthreads();
    g_g[t * 512 + tid]       = gv0 * s_scale * norm_w[tid];
    g_g[t * 512 + tid + 256] = gv1 * s_scale * norm_w[tid + 256];
}

// ---------------- launch ----------------
extern "C" void kernel_launch(void* const* d_in, const int* in_sizes, int n_in,
                              void* d_out, int out_size) {
    const float* x         = (const float*)d_in[0];
    const float* ln_gamma  = (const float*)d_in[1];
    const float* ln_beta   = (const float*)d_in[2];
    const float* in_proj_w = (const float*)d_in[3];
    const float* conv_w    = (const float*)d_in[4];
    const float* conv_b    = (const float*)d_in[5];
    const float* dt_bias   = (const float*)d_in[6];
    const float* A_log     = (const float*)d_in[7];
    const float* Dv        = (const float*)d_in[8];
    const float* norm_w    = (const float*)d_in[9];
    const float* out_proj_w= (const float*)d_in[10];
    const int*   pts       = (const int*)d_in[11];
    float* out = (float*)d_out;

    const int SMEM_GEMM  = 4 * 4608 * 4;                               // 73728
    const int SMEM_CONV  = 35 * 256 * 4;                               // 35840
    const int SMEM_CHUNK = (128 * 132 + 64 * 132 + 384) * 4;
    const int SMEM_YOFF  = (128 * 132 + 64 * 132 + 128) * 4;
    cudaFuncSetAttribute(k_gemm_tc, cudaFuncAttributeMaxDynamicSharedMemorySize, SMEM_GEMM);
    cudaFuncSetAttribute(k_conv,  cudaFuncAttributeMaxDynamicSharedMemorySize, SMEM_CONV);
    cudaFuncSetAttribute(k_chunk, cudaFuncAttributeMaxDynamicSharedMemorySize, SMEM_CHUNK);
    cudaFuncSetAttribute(k_yoff,  cudaFuncAttributeMaxDynamicSharedMemorySize, SMEM_YOFF);

    float *p_xn, *p_zx, *p_B, *p_C, *p_M, *p_g;
    cudaGetSymbolAddress((void**)&p_xn, g_xn);
    cudaGetSymbolAddress((void**)&p_zx, g_zx);
    cudaGetSymbolAddress((void**)&p_B,  g_Bmat);
    cudaGetSymbolAddress((void**)&p_C,  g_Cmat);
    cudaGetSymbolAddress((void**)&p_M,  g_M);
    cudaGetSymbolAddress((void**)&p_g,  g_g);

    k_ln<<<T_TOTAL, 256>>>(x, ln_gamma, ln_beta, in_proj_w);
    // cols 1280-1287 (dt_raw) are never consumed -> 10 column-blocks (1280 cols)
    k_gemm_tc<<<dim3(10, 512, 1), 256, SMEM_GEMM>>>(p_xn, in_proj_w, p_zx,
                                                    T_TOTAL, D_IN_PROJ, D_MODEL, 0, 0, 0, 0);
    k_conv<<<dim3(3, 2048), 256, SMEM_CONV>>>(conv_w, conv_b, dt_bias, A_log, pts);
    k_cumsum<<<512, 256>>>();
    k_gemm_tc<<<dim3(1, 1, 512), 256, SMEM_GEMM>>>(p_C, p_B, p_M,
                                                   128, 128, 128, 16384, 16384, 16384, 1);
    k_chunk<<<dim3(512, 8), 256, SMEM_CHUNK>>>(Dv);
    k_scan<<<256, 256>>>();
    k_yoff<<<dim3(512, 8), 256, SMEM_YOFF>>>();
    k_gate<<<T_TOTAL, 256>>>(norm_w);
    k_gemm_tc<<<dim3(2, 512, 1), 256, SMEM_GEMM>>>(p_g, out_proj_w, out,
                                                   T_TOTAL, D_MODEL, D_INNER, 0, 0, 0, 0);
}

// round 14
// speedup vs baseline: 1.4478x; 1.1423x over previous
#include <cuda_runtime.h>
#include <cuda_bf16.h>
#include <stdint.h>
#include <math.h>

#define T_TOTAL 65536
#define D_MODEL 256
#define D_INNER 512
#define HEADDIM 64
#define NHEADS 8
#define DSTATE 128
#define CHUNK 128
#define CONV_DIM 768
#define ZXS 1280
#define NCHUNK 512
#define NEGV -10000.0f

// ---------------- scratch ----------------
static __device__ float g_xn[T_TOTAL * D_MODEL];
static __device__ float g_zx[T_TOTAL * ZXS];
static __device__ float g_dtraw[T_TOTAL * NHEADS];
static __device__ float g_dt[T_TOTAL * NHEADS];
static __device__ float g_xh[T_TOTAL * D_INNER];
static __device__ float g_Bmat[T_TOTAL * DSTATE];
static __device__ float g_Cmat[T_TOTAL * DSTATE];
static __device__ float g_a[T_TOTAL * NHEADS];
static __device__ float g_Acum[T_TOTAL * NHEADS];
static __device__ float g_cd[NCHUNK * NHEADS];
static __device__ float g_M[NCHUNK * CHUNK * CHUNK];
static __device__ float g_cs[NCHUNK * NHEADS * HEADDIM * DSTATE];
static __device__ float g_ps[NCHUNK * NHEADS * HEADDIM * DSTATE];
static __device__ float g_y[T_TOTAL * D_INNER];
static __device__ float g_g[T_TOTAL * D_INNER];

// ---------------- helpers ----------------
__device__ __forceinline__ float to_tf32(float f) {
    unsigned u; asm("cvt.rna.tf32.f32 %0, %1;" : "=r"(u) : "f"(f));
    return __uint_as_float(u);
}
__device__ __forceinline__ float4 cvt4(float4 v) {
    return make_float4(to_tf32(v.x), to_tf32(v.y), to_tf32(v.z), to_tf32(v.w));
}

#define LDSM4(r0, r1, r2, r3, addr) \
    asm volatile("ldmatrix.sync.aligned.m8n8.x4.shared.b16 {%0,%1,%2,%3}, [%4];" \
                 : "=r"(r0), "=r"(r1), "=r"(r2), "=r"(r3) : "r"(addr))

#define MMA_TF32(d, a, b0, b1) \
    asm volatile("mma.sync.aligned.m16n8k8.row.col.f32.tf32.tf32.f32 " \
                 "{%0,%1,%2,%3}, {%4,%5,%6,%7}, {%8,%9}, {%0,%1,%2,%3};" \
                 : "+f"(d[0]), "+f"(d[1]), "+f"(d[2]), "+f"(d[3]) \
                 : "r"(a[0]), "r"(a[1]), "r"(a[2]), "r"(a[3]), "r"(b0), "r"(b1))

// ---------------- LayerNorm + fused fp32 dt_raw (one head per warp) ----------------
__global__ __launch_bounds__(256) void k_ln(const float* __restrict__ x,
                                            const float* __restrict__ gamma,
                                            const float* __restrict__ beta,
                                            const float* __restrict__ W) {
    int t = blockIdx.x, tid = threadIdx.x;
    int warp = tid >> 5, lane = tid & 31;
    float v = x[t * 256 + tid];
    float s = v, s2 = v * v;
    #pragma unroll
    for (int o = 16; o; o >>= 1) {
        s  += __shfl_xor_sync(0xffffffffu, s, o);
        s2 += __shfl_xor_sync(0xffffffffu, s2, o);
    }
    __shared__ float ws[8], ws2[8];
    if (lane == 0) { ws[warp] = s; ws2[warp] = s2; }
    __syncthreads();
    __shared__ float s_mu, s_rstd;
    if (tid == 0) {
        float a = 0.f, b = 0.f;
        #pragma unroll
        for (int i = 0; i < 8; i++) { a += ws[i]; b += ws2[i]; }
        float mu = a * (1.f / 256.f);
        float var = b * (1.f / 256.f) - mu * mu;
        s_mu = mu; s_rstd = rsqrtf(var + 1e-5f);
    }
    __syncthreads();
    float xn = (v - s_mu) * s_rstd * gamma[tid] + beta[tid];
    g_xn[t * 256 + tid] = xn;
    __shared__ float sxn[256];
    sxn[tid] = xn;
    __syncthreads();
    const float* w8 = W + (long)(1280 + warp) * 256;
    float d = 0.f;
    #pragma unroll
    for (int i = 0; i < 8; i++) {
        int k = lane + 32 * i;
        d += sxn[k] * w8[k];
    }
    #pragma unroll
    for (int o = 16; o; o >>= 1) d += __shfl_xor_sync(0xffffffffu, d, o);
    if (lane == 0) g_dtraw[t * 8 + warp] = d;
}

// ---------------- tf32 GEMM (double-buffered): C[M,N]=A[M,K]*B[N,K]^T, batched ----------------
__global__ __launch_bounds__(256) void k_gemm_tc(const float* __restrict__ A,
                                                 const float* __restrict__ B,
                                                 float* __restrict__ C,
                                                 int M, int N, int K,
                                                 long sA, long sB, long sC, int tri) {
    extern __shared__ float smg[];   // [A0|A1|B0|B1], 4608 floats each
    A += (long)blockIdx.z * sA;
    B += (long)blockIdx.z * sB;
    C += (long)blockIdx.z * sC;
    const int tid = threadIdx.x;
    const int warp = tid >> 5, lane = tid & 31;
    const int wm = (warp >> 1) * 32;
    const int wn = (warp & 1) * 64;
    const long m0 = (long)blockIdx.y * 128;
    const int n0 = blockIdx.x * 128;
    const int lr = tid >> 1;
    const int lc = tid & 1;
    const int lr16 = lane & 15;
    const int khalf = (lane >> 4) * 4;
    float acc[2][8][4] = {};
    const int ntiles = K >> 5;
    const bool nvalid = (n0 + lr) < N;
    const bool skipw = tri && (wn >= wm + 32);
    const float* Arow = A + (m0 + lr) * K;
    const float* Brow = B + (long)(n0 + lr) * K;
    float4 va[4], vb[4];

    #pragma unroll
    for (int i = 0; i < 4; i++) {
        int cc = (lc + 2 * i) * 4;
        va[i] = *(const float4*)(Arow + cc);
        vb[i] = nvalid ? *(const float4*)(Brow + cc) : make_float4(0.f, 0.f, 0.f, 0.f);
    }
    #pragma unroll
    for (int i = 0; i < 4; i++) {
        int cc = (lc + 2 * i) * 4;
        *(float4*)&smg[lr * 36 + cc]        = cvt4(va[i]);
        *(float4*)&smg[9216 + lr * 36 + cc] = cvt4(vb[i]);
    }
    __syncthreads();

    for (int kt = 0; kt < ntiles; kt++) {
        if (kt + 1 < ntiles) {
            int k0 = (kt + 1) << 5;
            #pragma unroll
            for (int i = 0; i < 4; i++) {
                int cc = (lc + 2 * i) * 4;
                va[i] = *(const float4*)(Arow + k0 + cc);
                vb[i] = nvalid ? *(const float4*)(Brow + k0 + cc) : make_float4(0.f, 0.f, 0.f, 0.f);
            }
        }
        if (!skipw) {
            const unsigned sAb = (unsigned)__cvta_generic_to_shared(smg + (kt & 1) * 4608);
            const unsigned sBb = (unsigned)__cvta_generic_to_shared(smg + 9216 + (kt & 1) * 4608);
            #pragma unroll
            for (int kk = 0; kk < 32; kk += 8) {
                unsigned af[2][4];
                #pragma unroll
                for (int mt = 0; mt < 2; mt++) {
                    unsigned ad = sAb + (unsigned)(((wm + mt * 16 + lr16) * 36 + kk + khalf) * 4);
                    LDSM4(af[mt][0], af[mt][1], af[mt][2], af[mt][3], ad);
                }
                unsigned bf[4][4];
                #pragma unroll
                for (int nt = 0; nt < 4; nt++) {
                    unsigned bd = sBb + (unsigned)(((wn + nt * 16 + lr16) * 36 + kk + khalf) * 4);
                    LDSM4(bf[nt][0], bf[nt][1], bf[nt][2], bf[nt][3], bd);
                }
                #pragma unroll
                for (int mt = 0; mt < 2; mt++)
                    #pragma unroll
                    for (int nt = 0; nt < 4; nt++) {
                        MMA_TF32(acc[mt][nt * 2 + 0], af[mt], bf[nt][0], bf[nt][2]);
                        MMA_TF32(acc[mt][nt * 2 + 1], af[mt], bf[nt][1], bf[nt][3]);
                    }
            }
        }
        if (kt + 1 < ntiles) {
            float* dA = smg + ((kt + 1) & 1) * 4608;
            float* dB = smg + 9216 + ((kt + 1) & 1) * 4608;
            #pragma unroll
            for (int i = 0; i < 4; i++) {
                int cc = (lc + 2 * i) * 4;
                *(float4*)&dA[lr * 36 + cc] = cvt4(va[i]);
                *(float4*)&dB[lr * 36 + cc] = cvt4(vb[i]);
            }
            __syncthreads();
        }
    }
    if (skipw) return;
    const int g = lane >> 2, tq = lane & 3;
    #pragma unroll
    for (int mt = 0; mt < 2; mt++) {
        long m = m0 + wm + mt * 16 + g;
        #pragma unroll
        for (int j = 0; j < 8; j++) {
            int n = n0 + wn + j * 8 + 2 * tq;
            if (n < N) {
                *(float2*)&C[m * N + n]       = make_float2(acc[mt][j][0], acc[mt][j][1]);
                *(float2*)&C[(m + 8) * N + n] = make_float2(acc[mt][j][2], acc[mt][j][3]);
            }
        }
    }
}

// ---------------- tiled conv + SiLU + splits + dt/a (32-token tiles) ----------------
__global__ __launch_bounds__(256) void k_conv(const float* __restrict__ conv_w,
                                              const float* __restrict__ conv_b,
                                              const float* __restrict__ dt_bias,
                                              const float* __restrict__ A_log,
                                              const int* __restrict__ pts) {
    extern __shared__ float s_in[];          // 35 * 256
    __shared__ int s_v[32];
    int cx = blockIdx.x, tid = threadIdx.x;
    long t0 = (long)blockIdx.y * 32;
    int c0 = cx * 256;
    for (int i = tid; i < 35 * 64; i += 256) {
        int row = i >> 6, c4 = (i & 63) * 4;
        long t = t0 - 3 + row;
        float4 v = (t >= 0) ? *(const float4*)(g_zx + t * ZXS + 512 + c0 + c4)
                            : make_float4(0.f, 0.f, 0.f, 0.f);
        *(float4*)&s_in[row * 256 + c4] = v;
    }
    if (tid < 32) {
        int t = (int)t0 + tid;
        int b = 0; bool s0 = false, s1 = false, s2 = false;
        #pragma unroll
        for (int j = 0; j < 8; j++) {
            if (b == t) s0 = true;
            if (b == t - 1) s1 = true;
            if (b == t - 2) s2 = true;
            b += pts[j];
        }
        bool v1 = !s0, v2 = v1 && !s1, v3 = v2 && !s2;
        s_v[tid] = (v1 ? 1 : 0) | (v2 ? 2 : 0) | (v3 ? 4 : 0) | (s0 ? 8 : 0);
    }
    __syncthreads();
    if (cx == 0) {
        int tok = tid >> 3, h = tid & 7;
        long t = t0 + tok;
        float xr = g_dtraw[t * 8 + h] + dt_bias[h];
        float dt = (xr > 20.f) ? xr : log1pf(expf(xr));
        g_dt[t * 8 + h] = dt;
        float a = -expf(A_log[h]) * dt;
        if (s_v[tok] & 8) a = NEGV;
        g_a[(((int)t >> 7) * 8 + h) * 128 + ((int)t & 127)] = a;
    }
    int ch = tid;
    float4 w = *(const float4*)(conv_w + (c0 + ch) * 4);
    float bias = conv_b[c0 + ch];
    #pragma unroll 4
    for (int tok = 0; tok < 32; tok++) {
        int m = s_v[tok];
        float acc = bias + s_in[(tok + 3) * 256 + ch] * w.w;
        if (m & 1) acc += s_in[(tok + 2) * 256 + ch] * w.z;
        if (m & 2) acc += s_in[(tok + 1) * 256 + ch] * w.y;
        if (m & 4) acc += s_in[(tok + 0) * 256 + ch] * w.x;
        float v = acc / (1.f + __expf(-acc));
        long t = t0 + tok;
        if (cx < 2) g_xh[t * 512 + c0 + ch] = v;
        else if (ch < 128) g_Bmat[t * 128 + ch] = v;
        else g_Cmat[t * 128 + (ch - 128)] = v;
    }
}

// ---------------- per-(chunk,head) cumsum of a ----------------
__global__ __launch_bounds__(256) void k_cumsum() {
    int idx = blockIdx.x * 8 + (threadIdx.x >> 5);
    int lane = threadIdx.x & 31;
    float4 v4 = *(const float4*)(g_a + idx * 128 + lane * 4);
    float p0 = v4.x, p1 = p0 + v4.y, p2 = p1 + v4.z, p3 = p2 + v4.w;
    float e = p3;
    #pragma unroll
    for (int o = 1; o < 32; o <<= 1) {
        float n = __shfl_up_sync(0xffffffffu, e, o);
        if (lane >= o) e += n;
    }
    float ex = e - p3;
    *(float4*)(g_Acum + idx * 128 + lane * 4) =
        make_float4(ex + p0, ex + p1, ex + p2, ex + p3);
    if (lane == 31) g_cd[idx] = expf(ex + p3);
}

// ---------------- k_chunk: Ydiag (+D*xh) and chunk_states via tf32 mma ----------------
__global__ __launch_bounds__(256) void k_chunk(const float* __restrict__ Dp) {
    extern __shared__ float sm[];
    float* sP   = sm;                   // 128 x 132
    float* sXT  = sm + 128 * 132;       // 64 x 132
    float* sAc  = sXT + 64 * 132;
    float* sDt  = sAc + 128;
    float* sDec = sDt + 128;
    int c = blockIdx.x, h = blockIdx.y, tid = threadIdx.x;
    int warp = tid >> 5, lane = tid & 31;
    int lr16 = lane & 15, khalf = (lane >> 4) * 4;
    const unsigned sPb = (unsigned)__cvta_generic_to_shared(sP);
    const unsigned sXb = (unsigned)__cvta_generic_to_shared(sXT);

    if (tid < 128) {
        sAc[tid] = g_Acum[(c * 8 + h) * 128 + tid];
        sDt[tid] = g_dt[((long)c * 128 + tid) * 8 + h];
    }
    __syncthreads();
    float alast = sAc[127];
    if (tid < 128) sDec[tid] = __expf(alast - sAc[tid]);
    const float* Xg = g_xh + (long)c * 128 * 512 + h * 64;
    for (int i = tid; i < 8192; i += 256) {
        int s = i >> 6, p = i & 63;
        sXT[p * 132 + s] = to_tf32(Xg[s * 512 + p] * sDt[s]);
    }
    const float* Mg = g_M + (long)c * 16384;
    for (int i = tid; i < 16384; i += 256) {
        int q = i >> 7, s = i & 127;
        sP[q * 132 + s] = (s <= q) ? to_tf32(Mg[i] * __expf(sAc[q] - sAc[s])) : 0.f;
    }
    __syncthreads();

    float acc[8][4] = {};
    int wm = warp * 16;
    for (int kk = 0; kk < wm + 16; kk += 8) {
        unsigned af[4];
        unsigned ad = sPb + (unsigned)(((wm + lr16) * 132 + kk + khalf) * 4);
        LDSM4(af[0], af[1], af[2], af[3], ad);
        unsigned bf[4][4];
        #pragma unroll
        for (int nt = 0; nt < 4; nt++) {
            unsigned bd = sXb + (unsigned)(((nt * 16 + lr16) * 132 + kk + khalf) * 4);
            LDSM4(bf[nt][0], bf[nt][1], bf[nt][2], bf[nt][3], bd);
        }
        #pragma unroll
        for (int nt = 0; nt < 4; nt++) {
            MMA_TF32(acc[nt * 2 + 0], af, bf[nt][0], bf[nt][2]);
            MMA_TF32(acc[nt * 2 + 1], af, bf[nt][1], bf[nt][3]);
        }
    }
    float Dh = Dp[h];
    int g = lane >> 2, tq = lane & 3;
    {
        long r0 = ((long)c * 128 + wm + g) * 512 + h * 64;
        long r1 = r0 + 8 * 512;
        #pragma unroll
        for (int j = 0; j < 8; j++) {
            int n = j * 8 + 2 * tq;
            float2 x0 = *(const float2*)&g_xh[r0 + n];
            float2 x1 = *(const float2*)&g_xh[r1 + n];
            *(float2*)&g_y[r0 + n] = make_float2(acc[j][0] + Dh * x0.x, acc[j][1] + Dh * x0.y);
            *(float2*)&g_y[r1 + n] = make_float2(acc[j][2] + Dh * x1.x, acc[j][3] + Dh * x1.y);
        }
    }
    __syncthreads();

    for (int i = tid; i < 8192; i += 256) {
        int p = i >> 7, s = i & 127;
        sXT[p * 132 + s] = to_tf32(sXT[p * 132 + s] * sDec[s]);
    }
    const float* Bg = g_Bmat + (long)c * 16384;
    for (int i = tid; i < 16384; i += 256) {
        int s = i >> 7, n = i & 127;
        sP[n * 132 + s] = to_tf32(Bg[i]);
    }
    __syncthreads();

    float acc2[8][4] = {};
    int wm2 = (warp & 3) * 16, wn2 = (warp >> 2) * 64;
    for (int kk = 0; kk < 128; kk += 8) {
        unsigned af[4];
        unsigned ad = sXb + (unsigned)(((wm2 + lr16) * 132 + kk + khalf) * 4);
        LDSM4(af[0], af[1], af[2], af[3], ad);
        unsigned bf[4][4];
        #pragma unroll
        for (int nt = 0; nt < 4; nt++) {
            unsigned bd = sPb + (unsigned)(((wn2 + nt * 16 + lr16) * 132 + kk + khalf) * 4);
            LDSM4(bf[nt][0], bf[nt][1], bf[nt][2], bf[nt][3], bd);
        }
        #pragma unroll
        for (int nt = 0; nt < 4; nt++) {
            MMA_TF32(acc2[nt * 2 + 0], af, bf[nt][0], bf[nt][2]);
            MMA_TF32(acc2[nt * 2 + 1], af, bf[nt][1], bf[nt][3]);
        }
    }
    float* So = g_cs + ((long)c * 8 + h) * 8192;
    #pragma unroll
    for (int j = 0; j < 8; j++) {
        int n = wn2 + j * 8 + 2 * tq;
        int p = wm2 + g;
        *(float2*)&So[p * 128 + n]       = make_float2(acc2[j][0], acc2[j][1]);
        *(float2*)&So[(p + 8) * 128 + n] = make_float2(acc2[j][2], acc2[j][3]);
    }
}

// ---------------- inter-chunk scan (4-deep load prefetch) ----------------
__global__ __launch_bounds__(256) void k_scan() {
    int e = blockIdx.x * 256 + threadIdx.x;
    int h = e >> 13;
    float st = 0.f;
    const float* cdp = g_cd + h;
    const float* csp = g_cs + e;
    float* psp = g_ps + e;
    for (int c = 0; c < NCHUNK; c += 4) {
        float cs0 = csp[(long)(c + 0) * 65536];
        float cs1 = csp[(long)(c + 1) * 65536];
        float cs2 = csp[(long)(c + 2) * 65536];
        float cs3 = csp[(long)(c + 3) * 65536];
        float cd0 = cdp[(c + 0) * 8];
        float cd1 = cdp[(c + 1) * 8];
        float cd2 = cdp[(c + 2) * 8];
        float cd3 = cdp[(c + 3) * 8];
        psp[(long)(c + 0) * 65536] = st; st = st * cd0 + cs0;
        psp[(long)(c + 1) * 65536] = st; st = st * cd1 + cs1;
        psp[(long)(c + 2) * 65536] = st; st = st * cd2 + cs2;
        psp[(long)(c + 3) * 65536] = st; st = st * cd3 + cs3;
    }
}

// ---------------- k_yoff: one block per chunk, C tile reused across 8 heads ----------------
__global__ __launch_bounds__(256) void k_yoff() {
    extern __shared__ float sm[];
    float* sC  = sm;                    // 128 x 132
    float* sPS = sm + 128 * 132;        // 64 x 132
    float* sAc = sPS + 64 * 132;        // 128
    int c = blockIdx.x, tid = threadIdx.x;
    int warp = tid >> 5, lane = tid & 31;
    int lr16 = lane & 15, khalf = (lane >> 4) * 4;
    const unsigned sCb = (unsigned)__cvta_generic_to_shared(sC);
    const unsigned sSb = (unsigned)__cvta_generic_to_shared(sPS);

    const float* Cg = g_Cmat + (long)c * 16384;
    for (int i = tid; i < 16384; i += 256) {
        int q = i >> 7, n = i & 127;
        sC[q * 132 + n] = to_tf32(Cg[i]);
    }

    int g = lane >> 2, tq = lane & 3;
    int wm = warp * 16;

    for (int h = 0; h < 8; h++) {
        if (tid < 128) sAc[tid] = g_Acum[(c * 8 + h) * 128 + tid];
        const float* Pg = g_ps + ((long)c * 8 + h) * 8192;
        for (int i = tid; i < 8192; i += 256) {
            int p = i >> 7, n = i & 127;
            sPS[p * 132 + n] = to_tf32(Pg[i]);
        }
        __syncthreads();

        float acc[8][4] = {};
        for (int kk = 0; kk < 128; kk += 8) {
            unsigned af[4];
            unsigned ad = sCb + (unsigned)(((wm + lr16) * 132 + kk + khalf) * 4);
            LDSM4(af[0], af[1], af[2], af[3], ad);
            unsigned bf[4][4];
            #pragma unroll
            for (int nt = 0; nt < 4; nt++) {
                unsigned bd = sSb + (unsigned)(((nt * 16 + lr16) * 132 + kk + khalf) * 4);
                LDSM4(bf[nt][0], bf[nt][1], bf[nt][2], bf[nt][3], bd);
            }
            #pragma unroll
            for (int nt = 0; nt < 4; nt++) {
                MMA_TF32(acc[nt * 2 + 0], af, bf[nt][0], bf[nt][2]);
                MMA_TF32(acc[nt * 2 + 1], af, bf[nt][1], bf[nt][3]);
            }
        }
        float eq0 = __expf(sAc[wm + g]);
        float eq1 = __expf(sAc[wm + g + 8]);
        long r0 = ((long)c * 128 + wm + g) * 512 + h * 64;
        long r1 = r0 + 8 * 512;
        #pragma unroll
        for (int j = 0; j < 8; j++) {
            int n = j * 8 + 2 * tq;
            float2 y0 = *(const float2*)&g_y[r0 + n];
            float2 y1 = *(const float2*)&g_y[r1 + n];
            *(float2*)&g_y[r0 + n] = make_float2(y0.x + eq0 * acc[j][0], y0.y + eq0 * acc[j][1]);
            *(float2*)&g_y[r1 + n] = make_float2(y1.x + eq1 * acc[j][2], y1.y + eq1 * acc[j][3]);
        }
        __syncthreads();
    }
}

// ---------------- gated RMSNorm ----------------
__global__ __launch_bounds__(256) void k_gate(const float* __restrict__ norm_w) {
    int t = blockIdx.x, tid = threadIdx.x;
    float y0 = g_y[t * 512 + tid];
    float z0 = g_zx[(long)t * ZXS + tid];
    float gv0 = y0 * (z0 / (1.f + __expf(-z0)));
    float y1 = g_y[t * 512 + tid + 256];
    float z1 = g_zx[(long)t * ZXS + tid + 256];
    float gv1 = y1 * (z1 / (1.f + __expf(-z1)));
    float ss = gv0 * gv0 + gv1 * gv1;
    #pragma unroll
    for (int o = 16; o; o >>= 1) ss += __shfl_xor_sync(0xffffffffu, ss, o);
    __shared__ float ws[8];
    if ((tid & 31) == 0) ws[tid >> 5] = ss;
    __syncthreads();
    __shared__ float s_scale;
    if (tid == 0) {
        float a = 0.f;
        #pragma unroll
        for (int i = 0; i < 8; i++) a += ws[i];
        s_scale = rsqrtf(a * (1.f / 512.f) + 1e-5f);
    }
    __syncthreads();
    g_g[t * 512 + tid]       = gv0 * s_scale * norm_w[tid];
    g_g[t * 512 + tid + 256] = gv1 * s_scale * norm_w[tid + 256];
}

// ---------------- launch ----------------
extern "C" void kernel_launch(void* const* d_in, const int* in_sizes, int n_in,
                              void* d_out, int out_size) {
    const float* x         = (const float*)d_in[0];
    const float* ln_gamma  = (const float*)d_in[1];
    const float* ln_beta   = (const float*)d_in[2];
    const float* in_proj_w = (const float*)d_in[3];
    const float* conv_w    = (const float*)d_in[4];
    const float* conv_b    = (const float*)d_in[5];
    const float* dt_bias   = (const float*)d_in[6];
    const float* A_log     = (const float*)d_in[7];
    const float* Dv        = (const float*)d_in[8];
    const float* norm_w    = (const float*)d_in[9];
    const float* out_proj_w= (const float*)d_in[10];
    const int*   pts       = (const int*)d_in[11];
    float* out = (float*)d_out;

    const int SMEM_GEMM  = 4 * 4608 * 4;                               // 73728
    const int SMEM_CONV  = 35 * 256 * 4;                               // 35840
    const int SMEM_CHUNK = (128 * 132 + 64 * 132 + 384) * 4;
    const int SMEM_YOFF  = (128 * 132 + 64 * 132 + 128) * 4;
    cudaFuncSetAttribute(k_gemm_tc, cudaFuncAttributeMaxDynamicSharedMemorySize, SMEM_GEMM);
    cudaFuncSetAttribute(k_conv,  cudaFuncAttributeMaxDynamicSharedMemorySize, SMEM_CONV);
    cudaFuncSetAttribute(k_chunk, cudaFuncAttributeMaxDynamicSharedMemorySize, SMEM_CHUNK);
    cudaFuncSetAttribute(k_yoff,  cudaFuncAttributeMaxDynamicSharedMemorySize, SMEM_YOFF);

    float *p_xn, *p_zx, *p_B, *p_C, *p_M, *p_g;
    cudaGetSymbolAddress((void**)&p_xn, g_xn);
    cudaGetSymbolAddress((void**)&p_zx, g_zx);
    cudaGetSymbolAddress((void**)&p_B,  g_Bmat);
    cudaGetSymbolAddress((void**)&p_C,  g_Cmat);
    cudaGetSymbolAddress((void**)&p_M,  g_M);
    cudaGetSymbolAddress((void**)&p_g,  g_g);

    k_ln<<<T_TOTAL, 256>>>(x, ln_gamma, ln_beta, in_proj_w);
    // N=1280 (dt cols dropped): row stride 1280 = 5120B, 128B-aligned rows
    k_gemm_tc<<<dim3(10, 512, 1), 256, SMEM_GEMM>>>(p_xn, in_proj_w, p_zx,
                                                    T_TOTAL, ZXS, D_MODEL, 0, 0, 0, 0);
    k_conv<<<dim3(3, 2048), 256, SMEM_CONV>>>(conv_w, conv_b, dt_bias, A_log, pts);
    k_cumsum<<<512, 256>>>();
    k_gemm_tc<<<dim3(1, 1, 512), 256, SMEM_GEMM>>>(p_C, p_B, p_M,
                                                   128, 128, 128, 16384, 16384, 16384, 1);
    k_chunk<<<dim3(512, 8), 256, SMEM_CHUNK>>>(Dv);
    k_scan<<<256, 256>>>();
    k_yoff<<<512, 256, SMEM_YOFF>>>();
    k_gate<<<T_TOTAL, 256>>>(norm_w);
    k_gemm_tc<<<dim3(2, 512, 1), 256, SMEM_GEMM>>>(p_g, out_proj_w, out,
                                                   T_TOTAL, D_MODEL, D_INNER, 0, 0, 0, 0);
}